// round 7
// baseline (speedup 1.0000x reference)
#include <cuda_runtime.h>
#include <math.h>

#define BB    64
#define DD    256
#define HEADS 8
#define DH    32
#define NTOK  625
#define NPAD  640

// ---- scratch (device globals) ----
__device__ float g_q[BB*HEADS*NTOK*DH];
__device__ float g_k[BB*HEADS*NTOK*DH];
__device__ float g_v[BB*HEADS*NTOK*DH];
__device__ float g_bias[HEADS*NPAD*NPAD];
__device__ float g_o[BB*NTOK*DD];

// ================= bf16 split helpers =================
__device__ __forceinline__ unsigned packbf(float x0, float x1) {
    unsigned u;
    asm("cvt.rn.bf16x2.f32 %0, %1, %2;" : "=r"(u) : "f"(x1), "f"(x0));
    return u;
}
__device__ __forceinline__ void split2(float x0, float x1,
                                       unsigned &h, unsigned &l) {
    h = packbf(x0, x1);
    float h0 = __uint_as_float(h << 16);
    float h1 = __uint_as_float(h & 0xffff0000u);
    l = packbf(x0 - h0, x1 - h1);
}
__device__ __forceinline__ void mma16(float4 &d, const unsigned a[4],
                                      unsigned b0, unsigned b1) {
    asm volatile(
        "mma.sync.aligned.m16n8k16.row.col.f32.bf16.bf16.f32 "
        "{%0,%1,%2,%3}, {%4,%5,%6,%7}, {%8,%9}, {%0,%1,%2,%3};"
        : "+f"(d.x), "+f"(d.y), "+f"(d.z), "+f"(d.w)
        : "r"(a[0]), "r"(a[1]), "r"(a[2]), "r"(a[3]), "r"(b0), "r"(b1));
}
__device__ __forceinline__ void mma3(float4 &d, const unsigned ah[4],
                                     const unsigned al[4],
                                     unsigned bh0, unsigned bh1,
                                     unsigned bl0, unsigned bl1) {
    mma16(d, ah, bh0, bh1);
    mma16(d, ah, bl0, bl1);
    mma16(d, al, bh0, bh1);
}
// ================= ldmatrix helpers =================
__device__ __forceinline__ unsigned sptr(const void* p) {
    return (unsigned)__cvta_generic_to_shared(p);
}
__device__ __forceinline__ void ldsm4(unsigned r[4], unsigned addr) {
    asm volatile("ldmatrix.sync.aligned.m8n8.x4.shared.b16 {%0,%1,%2,%3}, [%4];"
        : "=r"(r[0]), "=r"(r[1]), "=r"(r[2]), "=r"(r[3]) : "r"(addr));
}
// split 8 floats (4 pairs) -> two uint4 (hi, lo)
__device__ __forceinline__ void split8(const float* f, uint4 &h4, uint4 &l4) {
    split2(f[0], f[1], h4.x, l4.x);
    split2(f[2], f[3], h4.y, l4.y);
    split2(f[4], f[5], h4.z, l4.z);
    split2(f[6], f[7], h4.w, l4.w);
}

// ============================================================
// Kernel 0: bias_fill (j-stride padded to 640)
// ============================================================
__global__ void bias_fill(const float* __restrict__ table,
                          const int*   __restrict__ rel) {
    int idx = blockIdx.x * blockDim.x + threadIdx.x;
    const int total = HEADS * NTOK * NTOK;
    if (idx >= total) return;
    int h = idx / (NTOK * NTOK);
    int r = idx - h * (NTOK * NTOK);
    int i = r / NTOK;
    int j = r - i * NTOK;
    g_bias[(h * NPAD + i) * NPAD + j] = table[rel[r] * HEADS + h];
}

// ============================================================
// Kernel 1: QKV projection, bf16 3-mma + LDSM + STS.128 staging
// + register prefetch. 128x64, K=256, 32 k per slab.
// ============================================================
__global__ __launch_bounds__(256) void qkv_mma(const float* __restrict__ x,
                                               const float* __restrict__ w) {
    __shared__ __align__(16) unsigned Ah[128][20], Al[128][20];
    __shared__ __align__(16) unsigned Bh[64][20],  Bl[64][20];

    int b  = blockIdx.z;
    int p0 = blockIdx.x * 128;
    int n0 = blockIdx.y * 64;
    int tid = threadIdx.x;
    int wid = tid >> 5, lane = tid & 31;
    int wm = wid & 3, wn = wid >> 2;
    int r = lane >> 2, c = lane & 3;
    const float* xb = x + (size_t)b * DD * NTOK;

    float4 acc[2][4];
    #pragma unroll
    for (int i = 0; i < 2; i++)
        #pragma unroll
        for (int j = 0; j < 4; j++) acc[i][j] = make_float4(0,0,0,0);

    int am   = tid & 127;
    int ahlf = tid >> 7;
    int bn   = tid & 63;
    int bq   = tid >> 6;
    bool ap_ok = (p0 + am) < NTOK;

    int aRow = lane & 15;
    int aSel = (lane >> 4) * 4;
    int bRow = ((lane >> 4) << 3) | (lane & 7);
    int bSel = ((lane >> 3) & 1) * 4;
    unsigned AhB = sptr(Ah), AlB = sptr(Al), BhB = sptr(Bh), BlB = sptr(Bl);

    float av[16], bw[8], av2[16], bw2[8];
    // preload slab 0
    #pragma unroll
    for (int i = 0; i < 16; i++) {
        int k = 16 * ahlf + i;
        av[i] = ap_ok ? xb[(size_t)k * NTOK + p0 + am] : 0.f;
    }
    #pragma unroll
    for (int i = 0; i < 8; i++)
        bw[i] = w[(size_t)(8 * bq + i) * (3*DD) + n0 + bn];

    for (int k0 = 0; k0 < DD; k0 += 32) {
        // ---- stage from regs (STS.128) ----
        {
            uint4 h4, l4;
            split8(&av[0], h4, l4);
            *(uint4*)&Ah[am][8*ahlf]     = h4;
            *(uint4*)&Al[am][8*ahlf]     = l4;
            split8(&av[8], h4, l4);
            *(uint4*)&Ah[am][8*ahlf + 4] = h4;
            *(uint4*)&Al[am][8*ahlf + 4] = l4;
            split8(bw, h4, l4);
            *(uint4*)&Bh[bn][4*bq] = h4;
            *(uint4*)&Bl[bn][4*bq] = l4;
        }
        __syncthreads();

        // ---- prefetch next slab (overlaps mma below) ----
        if (k0 + 32 < DD) {
            #pragma unroll
            for (int i = 0; i < 16; i++) {
                int k = k0 + 32 + 16 * ahlf + i;
                av2[i] = ap_ok ? xb[(size_t)k * NTOK + p0 + am] : 0.f;
            }
            #pragma unroll
            for (int i = 0; i < 8; i++)
                bw2[i] = w[(size_t)(k0 + 32 + 8 * bq + i) * (3*DD) + n0 + bn];
        }

        // ---- mma ----
        #pragma unroll
        for (int ktl = 0; ktl < 2; ktl++) {
            unsigned ah[2][4], al[2][4];
            #pragma unroll
            for (int mt = 0; mt < 2; mt++) {
                unsigned off = ((wm*32 + mt*16 + aRow) * 20 + ktl*8 + aSel) * 4u;
                ldsm4(ah[mt], AhB + off);
                ldsm4(al[mt], AlB + off);
            }
            unsigned bhf[4][2], blf[4][2];
            #pragma unroll
            for (int ntp = 0; ntp < 2; ntp++) {
                unsigned off = ((wn*32 + ntp*16 + bRow) * 20 + ktl*8 + bSel) * 4u;
                unsigned t[4];
                ldsm4(t, BhB + off);
                bhf[2*ntp][0] = t[0]; bhf[2*ntp][1] = t[1];
                bhf[2*ntp+1][0] = t[2]; bhf[2*ntp+1][1] = t[3];
                ldsm4(t, BlB + off);
                blf[2*ntp][0] = t[0]; blf[2*ntp][1] = t[1];
                blf[2*ntp+1][0] = t[2]; blf[2*ntp+1][1] = t[3];
            }
            #pragma unroll
            for (int nt = 0; nt < 4; nt++)
                #pragma unroll
                for (int mt = 0; mt < 2; mt++)
                    mma3(acc[mt][nt], ah[mt], al[mt],
                         bhf[nt][0], bhf[nt][1], blf[nt][0], blf[nt][1]);
        }
        __syncthreads();
        #pragma unroll
        for (int i = 0; i < 16; i++) av[i] = av2[i];
        #pragma unroll
        for (int i = 0; i < 8; i++) bw[i] = bw2[i];
    }

    // epilogue: scatter to g_q/g_k/g_v (bh, p, e); q pre-scaled
    #pragma unroll
    for (int nt = 0; nt < 4; nt++) {
        int ng0 = n0 + wn * 32 + nt * 8 + 2 * c;
        int which = ng0 >> 8;
        int h = (ng0 >> 5) & 7;
        int e = ng0 & 31;
        float* dst = (which == 0) ? g_q : (which == 1) ? g_k : g_v;
        float s = (which == 0) ? 0.17677669529663687f : 1.f;
        size_t base = (size_t)(b * HEADS + h) * NTOK * DH + e;
        #pragma unroll
        for (int mt = 0; mt < 2; mt++) {
            int p = p0 + wm * 32 + mt * 16 + r;
            if (p < NTOK)
                *(float2*)&dst[base + (size_t)p * DH] =
                    make_float2(acc[mt][nt].x * s, acc[mt][nt].y * s);
            if (p + 8 < NTOK)
                *(float2*)&dst[base + (size_t)(p + 8) * DH] =
                    make_float2(acc[mt][nt].z * s, acc[mt][nt].w * s);
        }
    }
}

// ============================================================
// Kernel 2: flash attention, bf16 3-mma + LDSM + STS.128 staging
// + register prefetch across KV tiles. P register-resident.
// ============================================================
__global__ __launch_bounds__(256) void attn_mma() {
    __shared__ __align__(16) unsigned Kh[64][20], Kl[64][20];
    __shared__ __align__(16) unsigned Vh[32][36], Vl[32][36];

    int tid = threadIdx.x;
    int wid = tid >> 5, lane = tid & 31;
    int r = lane >> 2, c = lane & 3;

    int q0 = blockIdx.x * 128;
    int bh = blockIdx.y;
    int h = bh & 7;
    const float* qb = g_q + (size_t)bh * NTOK * DH;
    const float* kb = g_k + (size_t)bh * NTOK * DH;
    const float* vb = g_v + (size_t)bh * NTOK * DH;

    int bRow = ((lane >> 4) << 3) | (lane & 7);
    int bSel = ((lane >> 3) & 1) * 4;
    unsigned KhB = sptr(Kh), KlB = sptr(Kl), VhB = sptr(Vh), VlB = sptr(Vl);

    // staging thread maps
    int kRow = tid >> 2, kE0 = (tid & 3) * 8;        // K: [row][e0..e0+7]
    int vE = tid & 31, vJq = tid >> 5;               // V: row e, j-words 4*vJq..+3

    // Q fragments (2 k16 over DH=32), pre-split, register-resident
    unsigned qh[2][4], ql[2][4];
    int pr = q0 + wid * 16 + r;
    #pragma unroll
    for (int kt = 0; kt < 2; kt++) {
        float2 q00 = (pr < NTOK)
            ? *(const float2*)&qb[(size_t)pr * DH + kt*16 + 2*c]
            : make_float2(0,0);
        float2 q01 = (pr < NTOK)
            ? *(const float2*)&qb[(size_t)pr * DH + kt*16 + 2*c + 8]
            : make_float2(0,0);
        float2 q10 = (pr + 8 < NTOK)
            ? *(const float2*)&qb[(size_t)(pr+8) * DH + kt*16 + 2*c]
            : make_float2(0,0);
        float2 q11 = (pr + 8 < NTOK)
            ? *(const float2*)&qb[(size_t)(pr+8) * DH + kt*16 + 2*c + 8]
            : make_float2(0,0);
        split2(q00.x, q00.y, qh[kt][0], ql[kt][0]);
        split2(q10.x, q10.y, qh[kt][1], ql[kt][1]);
        split2(q01.x, q01.y, qh[kt][2], ql[kt][2]);
        split2(q11.x, q11.y, qh[kt][3], ql[kt][3]);
    }

    float4 O[4];
    #pragma unroll
    for (int i = 0; i < 4; i++) O[i] = make_float4(0,0,0,0);
    float m0 = -INFINITY, m1 = -INFINITY, l0 = 0.f, l1 = 0.f;

    float kreg[8], vreg[8], kreg2[8], vreg2[8];
    // preload tile 0
    {
        int jp = kRow;
        if (jp < NTOK) {
            *(float4*)&kreg[0] = *(const float4*)&kb[(size_t)jp * DH + kE0];
            *(float4*)&kreg[4] = *(const float4*)&kb[(size_t)jp * DH + kE0 + 4];
        } else {
            #pragma unroll
            for (int i = 0; i < 8; i++) kreg[i] = 0.f;
        }
        #pragma unroll
        for (int jj = 0; jj < 8; jj++) {
            int jg = 8 * vJq + jj;
            vreg[jj] = (jg < NTOK) ? vb[(size_t)jg * DH + vE] : 0.f;
        }
    }

    for (int jt = 0; jt < 10; jt++) {
        int j0 = jt * 64;
        // ---- stage K/V from regs (STS.128) ----
        {
            uint4 h4, l4;
            split8(kreg, h4, l4);
            *(uint4*)&Kh[kRow][kE0 >> 1] = h4;
            *(uint4*)&Kl[kRow][kE0 >> 1] = l4;
            split8(vreg, h4, l4);
            *(uint4*)&Vh[vE][4*vJq] = h4;
            *(uint4*)&Vl[vE][4*vJq] = l4;
        }
        __syncthreads();

        // ---- prefetch next tile (overlaps compute) ----
        if (jt < 9) {
            int jn0 = j0 + 64;
            int jp = jn0 + kRow;
            if (jp < NTOK) {
                *(float4*)&kreg2[0] = *(const float4*)&kb[(size_t)jp * DH + kE0];
                *(float4*)&kreg2[4] = *(const float4*)&kb[(size_t)jp * DH + kE0 + 4];
            } else {
                #pragma unroll
                for (int i = 0; i < 8; i++) kreg2[i] = 0.f;
            }
            #pragma unroll
            for (int jj = 0; jj < 8; jj++) {
                int jg = jn0 + 8 * vJq + jj;
                vreg2[jj] = (jg < NTOK) ? vb[(size_t)jg * DH + vE] : 0.f;
            }
        }

        // ---- S = Q K^T (LDSM on K) ----
        float4 acc[8];
        #pragma unroll
        for (int i = 0; i < 8; i++) acc[i] = make_float4(0,0,0,0);
        #pragma unroll
        for (int kt = 0; kt < 2; kt++) {
            #pragma unroll
            for (int ntp = 0; ntp < 4; ntp++) {
                unsigned off = ((ntp*16 + bRow) * 20 + kt*8 + bSel) * 4u;
                unsigned th[4], tl[4];
                ldsm4(th, KhB + off);
                ldsm4(tl, KlB + off);
                mma3(acc[2*ntp  ], qh[kt], ql[kt], th[0], th[1], tl[0], tl[1]);
                mma3(acc[2*ntp+1], qh[kt], ql[kt], th[2], th[3], tl[2], tl[3]);
            }
        }

        // ---- bias + tail mask ----
        {
            const float* bp = g_bias + ((size_t)(h * NPAD + q0 + wid*16 + r)) * NPAD + j0;
            #pragma unroll
            for (int nt = 0; nt < 8; nt++) {
                float2 b0v = *(const float2*)&bp[nt*8 + 2*c];
                float2 b1v = *(const float2*)&bp[8*NPAD + nt*8 + 2*c];
                acc[nt].x += b0v.x; acc[nt].y += b0v.y;
                acc[nt].z += b1v.x; acc[nt].w += b1v.y;
            }
            if (j0 + 64 > NTOK) {
                #pragma unroll
                for (int nt = 0; nt < 8; nt++) {
                    int jc = j0 + nt*8 + 2*c;
                    if (jc     >= NTOK) { acc[nt].x = -1e30f; acc[nt].z = -1e30f; }
                    if (jc + 1 >= NTOK) { acc[nt].y = -1e30f; acc[nt].w = -1e30f; }
                }
            }
        }

        // ---- online softmax (quad reduce) ----
        float t0 = -INFINITY, t1 = -INFINITY;
        #pragma unroll
        for (int nt = 0; nt < 8; nt++) {
            t0 = fmaxf(t0, fmaxf(acc[nt].x, acc[nt].y));
            t1 = fmaxf(t1, fmaxf(acc[nt].z, acc[nt].w));
        }
        #pragma unroll
        for (int off = 1; off <= 2; off <<= 1) {
            t0 = fmaxf(t0, __shfl_xor_sync(0xffffffffu, t0, off));
            t1 = fmaxf(t1, __shfl_xor_sync(0xffffffffu, t1, off));
        }
        float mn0 = fmaxf(m0, t0), mn1 = fmaxf(m1, t1);
        float cor0 = __expf(m0 - mn0), cor1 = __expf(m1 - mn1);
        float s0 = 0.f, s1 = 0.f;
        #pragma unroll
        for (int nt = 0; nt < 8; nt++) {
            acc[nt].x = __expf(acc[nt].x - mn0);
            acc[nt].y = __expf(acc[nt].y - mn0);
            acc[nt].z = __expf(acc[nt].z - mn1);
            acc[nt].w = __expf(acc[nt].w - mn1);
            s0 += acc[nt].x + acc[nt].y;
            s1 += acc[nt].z + acc[nt].w;
        }
        #pragma unroll
        for (int off = 1; off <= 2; off <<= 1) {
            s0 += __shfl_xor_sync(0xffffffffu, s0, off);
            s1 += __shfl_xor_sync(0xffffffffu, s1, off);
        }
        l0 = l0 * cor0 + s0;  m0 = mn0;
        l1 = l1 * cor1 + s1;  m1 = mn1;
        #pragma unroll
        for (int i = 0; i < 4; i++) {
            O[i].x *= cor0; O[i].y *= cor0;
            O[i].z *= cor1; O[i].w *= cor1;
        }

        // ---- O += P V (LDSM on V; P register-resident) ----
        #pragma unroll
        for (int kt = 0; kt < 4; kt++) {
            unsigned ph[4], pl[4];
            split2(acc[2*kt  ].x, acc[2*kt  ].y, ph[0], pl[0]);
            split2(acc[2*kt  ].z, acc[2*kt  ].w, ph[1], pl[1]);
            split2(acc[2*kt+1].x, acc[2*kt+1].y, ph[2], pl[2]);
            split2(acc[2*kt+1].z, acc[2*kt+1].w, ph[3], pl[3]);
            #pragma unroll
            for (int ntp = 0; ntp < 2; ntp++) {
                unsigned off = ((ntp*16 + bRow) * 36 + kt*8 + bSel) * 4u;
                unsigned th[4], tl[4];
                ldsm4(th, VhB + off);
                ldsm4(tl, VlB + off);
                mma3(O[2*ntp  ], ph, pl, th[0], th[1], tl[0], tl[1]);
                mma3(O[2*ntp+1], ph, pl, th[2], th[3], tl[2], tl[3]);
            }
        }
        __syncthreads();

        #pragma unroll
        for (int i = 0; i < 8; i++) { kreg[i] = kreg2[i]; vreg[i] = vreg2[i]; }
    }

    // epilogue
    float inv0 = 1.f / l0, inv1 = 1.f / l1;
    float* ob = g_o + (size_t)(bh >> 3) * NTOK * DD + h * DH;
    #pragma unroll
    for (int nt = 0; nt < 4; nt++) {
        int e = nt*8 + 2*c;
        int p = q0 + wid*16 + r;
        if (p < NTOK)
            *(float2*)&ob[(size_t)p * DD + e] =
                make_float2(O[nt].x * inv0, O[nt].y * inv0);
        if (p + 8 < NTOK)
            *(float2*)&ob[(size_t)(p + 8) * DD + e] =
                make_float2(O[nt].z * inv1, O[nt].w * inv1);
    }
}

// ============================================================
// Kernel 3: output projection, bf16 3-mma + LDSM + STS.128
// + register prefetch + transposed store.
// ============================================================
#define OUT_CS_WORDS (128*69)   // 8832 > AB words (2*128*20 + 2*64*20 = 7680)
#define OUT_SM_WORDS OUT_CS_WORDS

__global__ __launch_bounds__(256) void out_mma(const float* __restrict__ w,
                                               float* __restrict__ out) {
    __shared__ __align__(16) unsigned smbuf[OUT_SM_WORDS];
    unsigned (*Ah)[20] = (unsigned(*)[20])smbuf;
    unsigned (*Al)[20] = (unsigned(*)[20])(smbuf + 128*20);
    unsigned (*Bh)[20] = (unsigned(*)[20])(smbuf + 2*128*20);
    unsigned (*Bl)[20] = (unsigned(*)[20])(smbuf + 2*128*20 + 64*20);
    float    (*Cs)[69] = (float(*)[69])smbuf;

    int b  = blockIdx.z;
    int p0 = blockIdx.x * 128;
    int n0 = blockIdx.y * 64;
    int tid = threadIdx.x;
    int wid = tid >> 5, lane = tid & 31;
    int wm = wid & 3, wn = wid >> 2;
    int r = lane >> 2, c = lane & 3;

    float4 acc[2][4];
    #pragma unroll
    for (int i = 0; i < 2; i++)
        #pragma unroll
        for (int j = 0; j < 4; j++) acc[i][j] = make_float4(0,0,0,0);

    int am   = tid >> 1;
    int ahlf = tid & 1;
    int bn   = tid & 63;
    int bq   = tid >> 6;
    bool ap_ok = (p0 + am) < NTOK;

    int aRow = lane & 15;
    int aSel = (lane >> 4) * 4;
    int bRow = ((lane >> 4) << 3) | (lane & 7);
    int bSel = ((lane >> 3) & 1) * 4;
    unsigned AhB = sptr(Ah), AlB = sptr(Al), BhB = sptr(Bh), BlB = sptr(Bl);

    float av[16], bw[8], av2[16], bw2[8];
    // preload slab 0
    {
        if (ap_ok) {
            const float* src = &g_o[((size_t)b * NTOK + p0 + am) * DD + 16*ahlf];
            *(float4*)&av[0]  = *(const float4*)&src[0];
            *(float4*)&av[4]  = *(const float4*)&src[4];
            *(float4*)&av[8]  = *(const float4*)&src[8];
            *(float4*)&av[12] = *(const float4*)&src[12];
        } else {
            #pragma unroll
            for (int i = 0; i < 16; i++) av[i] = 0.f;
        }
        #pragma unroll
        for (int i = 0; i < 8; i++)
            bw[i] = w[(size_t)(8 * bq + i) * DD + n0 + bn];
    }

    for (int k0 = 0; k0 < DD; k0 += 32) {
        // ---- stage from regs (STS.128) ----
        {
            uint4 h4, l4;
            split8(&av[0], h4, l4);
            *(uint4*)&Ah[am][8*ahlf]     = h4;
            *(uint4*)&Al[am][8*ahlf]     = l4;
            split8(&av[8], h4, l4);
            *(uint4*)&Ah[am][8*ahlf + 4] = h4;
            *(uint4*)&Al[am][8*ahlf + 4] = l4;
            split8(bw, h4, l4);
            *(uint4*)&Bh[bn][4*bq] = h4;
            *(uint4*)&Bl[bn][4*bq] = l4;
        }
        __syncthreads();

        // ---- prefetch next slab ----
        if (k0 + 32 < DD) {
            if (ap_ok) {
                const float* src = &g_o[((size_t)b * NTOK + p0 + am) * DD + k0 + 32 + 16*ahlf];
                *(float4*)&av2[0]  = *(const float4*)&src[0];
                *(float4*)&av2[4]  = *(const float4*)&src[4];
                *(float4*)&av2[8]  = *(const float4*)&src[8];
                *(float4*)&av2[12] = *(const float4*)&src[12];
            } else {
                #pragma unroll
                for (int i = 0; i < 16; i++) av2[i] = 0.f;
            }
            #pragma unroll
            for (int i = 0; i < 8; i++)
                bw2[i] = w[(size_t)(k0 + 32 + 8 * bq + i) * DD + n0 + bn];
        }

        // ---- mma ----
        #pragma unroll
        for (int ktl = 0; ktl < 2; ktl++) {
            unsigned ah[2][4], al[2][4];
            #pragma unroll
            for (int mt = 0; mt < 2; mt++) {
                unsigned off = ((wm*32 + mt*16 + aRow) * 20 + ktl*8 + aSel) * 4u;
                ldsm4(ah[mt], AhB + off);
                ldsm4(al[mt], AlB + off);
            }
            unsigned bhf[4][2], blf[4][2];
            #pragma unroll
            for (int ntp = 0; ntp < 2; ntp++) {
                unsigned off = ((wn*32 + ntp*16 + bRow) * 20 + ktl*8 + bSel) * 4u;
                unsigned t[4];
                ldsm4(t, BhB + off);
                bhf[2*ntp][0] = t[0]; bhf[2*ntp][1] = t[1];
                bhf[2*ntp+1][0] = t[2]; bhf[2*ntp+1][1] = t[3];
                ldsm4(t, BlB + off);
                blf[2*ntp][0] = t[0]; blf[2*ntp][1] = t[1];
                blf[2*ntp+1][0] = t[2]; blf[2*ntp+1][1] = t[3];
            }
            #pragma unroll
            for (int nt = 0; nt < 4; nt++)
                #pragma unroll
                for (int mt = 0; mt < 2; mt++)
                    mma3(acc[mt][nt], ah[mt], al[mt],
                         bhf[nt][0], bhf[nt][1], blf[nt][0], blf[nt][1]);
        }
        __syncthreads();
        #pragma unroll
        for (int i = 0; i < 16; i++) av[i] = av2[i];
        #pragma unroll
        for (int i = 0; i < 8; i++) bw[i] = bw2[i];
    }

    // C -> smem (unioned) -> coalesced transposed store
    #pragma unroll
    for (int mt = 0; mt < 2; mt++) {
        int m = wm * 32 + mt * 16 + r;
        #pragma unroll
        for (int nt = 0; nt < 4; nt++) {
            int n = wn * 32 + nt * 8 + 2 * c;
            Cs[m    ][n    ] = acc[mt][nt].x;
            Cs[m    ][n + 1] = acc[mt][nt].y;
            Cs[m + 8][n    ] = acc[mt][nt].z;
            Cs[m + 8][n + 1] = acc[mt][nt].w;
        }
    }
    __syncthreads();

    #pragma unroll
    for (int it = 0; it < 32; it++) {
        int idx = it * 256 + tid;
        int n = idx >> 7;
        int m = idx & 127;
        int p = p0 + m;
        if (p < NTOK)
            out[((size_t)b * DD + n0 + n) * NTOK + p] = Cs[m][n];
    }
}

// ============================================================
extern "C" void kernel_launch(void* const* d_in, const int* in_sizes, int n_in,
                              void* d_out, int out_size) {
    const float* x          = (const float*)d_in[0];
    const float* w_qkv      = (const float*)d_in[1];
    const float* w_out      = (const float*)d_in[2];
    const float* bias_table = (const float*)d_in[3];
    const int*   rel        = (const int*)d_in[4];
    float* out = (float*)d_out;

    bias_fill<<<(HEADS * NTOK * NTOK + 255) / 256, 256>>>(bias_table, rel);
    qkv_mma<<<dim3(5, 12, BB), 256>>>(x, w_qkv);
    attn_mma<<<dim3(5, BB * HEADS), 256>>>();
    out_mma<<<dim3(5, 4, BB), 256>>>(w_out, out);
}

// round 9
// speedup vs baseline: 1.0698x; 1.0698x over previous
#include <cuda_runtime.h>
#include <math.h>

#define BB    64
#define DD    256
#define HEADS 8
#define DH    32
#define NTOK  625
#define NTOKP 640
#define NPAD  640
#define NBH   (BB*HEADS)

// ---- scratch (device globals, zero-initialized) ----
__device__ __align__(128) unsigned g_xh[(size_t)BB*NTOKP*128];
__device__ __align__(128) unsigned g_xl[(size_t)BB*NTOKP*128];
__device__ __align__(128) unsigned g_wqh[768*128];
__device__ __align__(128) unsigned g_wql[768*128];
__device__ __align__(128) unsigned g_woh[256*128];
__device__ __align__(128) unsigned g_wol[256*128];
__device__ __align__(128) unsigned g_qh[(size_t)NBH*NTOKP*16];
__device__ __align__(128) unsigned g_ql[(size_t)NBH*NTOKP*16];
__device__ __align__(128) unsigned g_kh[(size_t)NBH*NTOKP*16];
__device__ __align__(128) unsigned g_kl[(size_t)NBH*NTOKP*16];
__device__ __align__(128) float    g_v [(size_t)NBH*NTOK*DH];
__device__ __align__(128) unsigned g_vth[(size_t)NBH*32*320];
__device__ __align__(128) unsigned g_vtl[(size_t)NBH*32*320];
__device__ __align__(128) unsigned g_oh[(size_t)BB*NTOKP*128];
__device__ __align__(128) unsigned g_ol[(size_t)BB*NTOKP*128];
__device__ __align__(16)  float    g_bias[HEADS*NPAD*NPAD];

// ================= bf16 split helpers =================
__device__ __forceinline__ unsigned packbf(float x0, float x1) {
    unsigned u;
    asm("cvt.rn.bf16x2.f32 %0, %1, %2;" : "=r"(u) : "f"(x1), "f"(x0));
    return u;
}
__device__ __forceinline__ void split2(float x0, float x1,
                                       unsigned &h, unsigned &l) {
    h = packbf(x0, x1);
    float h0 = __uint_as_float(h << 16);
    float h1 = __uint_as_float(h & 0xffff0000u);
    l = packbf(x0 - h0, x1 - h1);
}
__device__ __forceinline__ void mma16(float4 &d, const unsigned a[4],
                                      unsigned b0, unsigned b1) {
    asm volatile(
        "mma.sync.aligned.m16n8k16.row.col.f32.bf16.bf16.f32 "
        "{%0,%1,%2,%3}, {%4,%5,%6,%7}, {%8,%9}, {%0,%1,%2,%3};"
        : "+f"(d.x), "+f"(d.y), "+f"(d.z), "+f"(d.w)
        : "r"(a[0]), "r"(a[1]), "r"(a[2]), "r"(a[3]), "r"(b0), "r"(b1));
}
__device__ __forceinline__ void mma3(float4 &d, const unsigned ah[4],
                                     const unsigned al[4],
                                     unsigned bh0, unsigned bh1,
                                     unsigned bl0, unsigned bl1) {
    mma16(d, ah, bh0, bh1);
    mma16(d, ah, bl0, bl1);
    mma16(d, al, bh0, bh1);
}
// ================= ldmatrix / cp.async helpers =================
__device__ __forceinline__ unsigned sptr(const void* p) {
    return (unsigned)__cvta_generic_to_shared(p);
}
__device__ __forceinline__ void ldsm4(unsigned r[4], unsigned addr) {
    asm volatile("ldmatrix.sync.aligned.m8n8.x4.shared.b16 {%0,%1,%2,%3}, [%4];"
        : "=r"(r[0]), "=r"(r[1]), "=r"(r[2]), "=r"(r[3]) : "r"(addr));
}
__device__ __forceinline__ void cpa16(unsigned dst, const void* src) {
    asm volatile("cp.async.cg.shared.global [%0], [%1], 16;" :: "r"(dst), "l"(src));
}
#define CP_COMMIT() asm volatile("cp.async.commit_group;")
#define CP_WAIT0()  asm volatile("cp.async.wait_group 0;")

// ============================================================
// Kernel 0: bias_fill
// ============================================================
__global__ void bias_fill(const float* __restrict__ table,
                          const int*   __restrict__ rel) {
    int idx = blockIdx.x * blockDim.x + threadIdx.x;
    const int total = HEADS * NTOK * NTOK;
    if (idx >= total) return;
    int h = idx / (NTOK * NTOK);
    int r = idx - h * (NTOK * NTOK);
    int i = r / NTOK;
    int j = r - i * NTOK;
    g_bias[(h * NPAD + i) * NPAD + j] = table[rel[r] * HEADS + h];
}

// ============================================================
// prep_w: split weights once into [n][k2-word] layouts
// ============================================================
__global__ void prep_w(const float* __restrict__ wq,
                       const float* __restrict__ wo) {
    int idx = blockIdx.x * 256 + threadIdx.x;
    if (idx < 768 * 128) {
        int k2 = idx / 768, n = idx - k2 * 768;
        split2(wq[(size_t)(2*k2) * 768 + n], wq[(size_t)(2*k2+1) * 768 + n],
               g_wqh[n*128 + k2], g_wql[n*128 + k2]);
    } else {
        int j = idx - 768 * 128;
        if (j < 256 * 128) {
            int k2 = j / 256, n = j - k2 * 256;
            split2(wo[(size_t)(2*k2) * 256 + n], wo[(size_t)(2*k2+1) * 256 + n],
                   g_woh[n*128 + k2], g_wol[n*128 + k2]);
        }
    }
}

// ============================================================
// prep_x: transpose+split x (b,k,p) -> word layout (b,p,[k2])
// ============================================================
__global__ __launch_bounds__(256) void prep_x(const float* __restrict__ x) {
    __shared__ float sm[64][65];
    int p0 = blockIdx.x * 64, k0 = blockIdx.y * 64, b = blockIdx.z;
    int t = threadIdx.x;
    int pp = t & 63, kk0 = t >> 6;
    const float* xb = x + ((size_t)b * DD + k0) * NTOK + p0;
    bool pok = (p0 + pp) < NTOK;
    #pragma unroll
    for (int i = 0; i < 16; i++) {
        int kk = kk0 + i * 4;
        sm[kk][pp] = pok ? xb[(size_t)kk * NTOK + pp] : 0.f;
    }
    __syncthreads();
    int row = t >> 2, wseg = t & 3;
    unsigned hw[8], lw[8];
    #pragma unroll
    for (int i = 0; i < 8; i++) {
        int j2 = wseg * 8 + i;
        split2(sm[2*j2][row], sm[2*j2+1][row], hw[i], lw[i]);
    }
    size_t base = ((size_t)b * NTOKP + p0 + row) * 128 + k0/2 + wseg*8;
    *(uint4*)&g_xh[base]     = *(uint4*)&hw[0];
    *(uint4*)&g_xh[base + 4] = *(uint4*)&hw[4];
    *(uint4*)&g_xl[base]     = *(uint4*)&lw[0];
    *(uint4*)&g_xl[base + 4] = *(uint4*)&lw[4];
}

// ============================================================
// prep_vt: transpose+split V (bh,j,e) -> word layout (bh,e,[j2])
// (zero tail rows j >= NTOK).  FIX R8: row stride 36 (144B, 16B
// multiple) so the float4 staging stores are aligned.
// ============================================================
__global__ __launch_bounds__(256) void prep_vt() {
    __shared__ float sm[64][36];
    int jt = blockIdx.x, bh = blockIdx.y;
    int j0 = jt * 64, t = threadIdx.x;
    int j = t >> 2, e0 = (t & 3) * 8;
    const float* vb = g_v + (size_t)bh * NTOK * DH;
    if (j0 + j < NTOK) {
        *(float4*)&sm[j][e0]     = *(const float4*)&vb[(size_t)(j0+j) * DH + e0];
        *(float4*)&sm[j][e0 + 4] = *(const float4*)&vb[(size_t)(j0+j) * DH + e0 + 4];
    } else {
        #pragma unroll
        for (int i = 0; i < 8; i++) sm[j][e0 + i] = 0.f;
    }
    __syncthreads();
    int e = t >> 3, wseg = t & 7;
    unsigned hw[4], lw[4];
    #pragma unroll
    for (int i = 0; i < 4; i++) {
        int j2 = wseg * 4 + i;
        split2(sm[2*j2][e], sm[2*j2+1][e], hw[i], lw[i]);
    }
    size_t base = ((size_t)bh * 32 + e) * 320 + jt*32 + wseg*4;
    *(uint4*)&g_vth[base] = *(uint4*)hw;
    *(uint4*)&g_vtl[base] = *(uint4*)lw;
}

// ============================================================
// Kernel 1: QKV projection. cp.async double-buffered staging,
// LDSM fragments, bf16 3-mma. 128x64 tile, K=256, 8 slabs of 32.
// Stage layout (words): Ah[128][20] Al Bh[64][20] Bl = 7680/stage.
// ============================================================
#define STG 7680
#define GEMM_SMEM (2*STG*4)   // 61440 B

__global__ __launch_bounds__(256) void qkv_mma() {
    extern __shared__ __align__(16) unsigned qsm[];
    int b  = blockIdx.z;
    int p0 = blockIdx.x * 128;
    int n0 = blockIdx.y * 64;
    int tid = threadIdx.x;
    int wid = tid >> 5, lane = tid & 31;
    int wm = wid & 3, wn = wid >> 2;
    int r = lane >> 2, c = lane & 3;
    unsigned smb = sptr(qsm);

    float4 acc[2][4];
    #pragma unroll
    for (int i = 0; i < 2; i++)
        #pragma unroll
        for (int j = 0; j < 4; j++) acc[i][j] = make_float4(0,0,0,0);

    int aRow = lane & 15;
    int aSel = (lane >> 4) * 4;
    int bRow = ((lane >> 4) << 3) | (lane & 7);
    int bSel = ((lane >> 3) & 1) * 4;

    int caRow = tid >> 1, caHalf = tid & 1;
    int cbRow = tid >> 2, cbSeg = tid & 3;
    size_t aSrc = ((size_t)b * NTOKP + p0 + caRow) * 128 + caHalf * 8;
    size_t bSrc = (size_t)(n0 + cbRow) * 128 + cbSeg * 4;

    auto copy_slab = [&](int slab, int buf) {
        unsigned sb = smb + buf * STG * 4;
        unsigned dA  = sb + (caRow*20 + caHalf*8) * 4;
        unsigned dAl = dA + 2560 * 4;
        const unsigned* sh = g_xh + aSrc + slab*16;
        const unsigned* sl = g_xl + aSrc + slab*16;
        cpa16(dA,       sh);  cpa16(dA  + 16, sh + 4);
        cpa16(dAl,      sl);  cpa16(dAl + 16, sl + 4);
        unsigned dB  = sb + (5120 + cbRow*20 + cbSeg*4) * 4;
        cpa16(dB,            g_wqh + bSrc + slab*16);
        cpa16(dB + 1280*4,   g_wql + bSrc + slab*16);
    };

    copy_slab(0, 0);
    CP_COMMIT();
    int buf = 0;
    for (int s = 0; s < 8; s++) {
        CP_WAIT0();
        __syncthreads();
        if (s < 7) { copy_slab(s + 1, buf ^ 1); CP_COMMIT(); }

        unsigned AhB = smb + buf * STG * 4;
        unsigned AlB = AhB + 2560 * 4;
        unsigned BhB = AhB + 5120 * 4;
        unsigned BlB = AhB + 6400 * 4;
        #pragma unroll
        for (int ktl = 0; ktl < 2; ktl++) {
            unsigned ah[2][4], al[2][4];
            #pragma unroll
            for (int mt = 0; mt < 2; mt++) {
                unsigned off = ((wm*32 + mt*16 + aRow) * 20 + ktl*8 + aSel) * 4u;
                ldsm4(ah[mt], AhB + off);
                ldsm4(al[mt], AlB + off);
            }
            unsigned bhf[4][2], blf[4][2];
            #pragma unroll
            for (int ntp = 0; ntp < 2; ntp++) {
                unsigned off = ((wn*32 + ntp*16 + bRow) * 20 + ktl*8 + bSel) * 4u;
                unsigned t4[4];
                ldsm4(t4, BhB + off);
                bhf[2*ntp][0] = t4[0]; bhf[2*ntp][1] = t4[1];
                bhf[2*ntp+1][0] = t4[2]; bhf[2*ntp+1][1] = t4[3];
                ldsm4(t4, BlB + off);
                blf[2*ntp][0] = t4[0]; blf[2*ntp][1] = t4[1];
                blf[2*ntp+1][0] = t4[2]; blf[2*ntp+1][1] = t4[3];
            }
            #pragma unroll
            for (int nt = 0; nt < 4; nt++)
                #pragma unroll
                for (int mt = 0; mt < 2; mt++)
                    mma3(acc[mt][nt], ah[mt], al[mt],
                         bhf[nt][0], bhf[nt][1], blf[nt][0], blf[nt][1]);
        }
        buf ^= 1;
    }

    // epilogue: q/k pre-split words; v fp32
    #pragma unroll
    for (int nt = 0; nt < 4; nt++) {
        int ng0 = n0 + wn * 32 + nt * 8 + 2 * c;
        int which = ng0 >> 8;
        int h = (ng0 >> 5) & 7;
        int e = ng0 & 31;
        int bhI = b * HEADS + h;
        float s = (which == 0) ? 0.17677669529663687f : 1.f;
        #pragma unroll
        for (int mt = 0; mt < 2; mt++) {
            int p = p0 + wm * 32 + mt * 16 + r;
            float4 a = acc[mt][nt];
            if (which == 2) {
                if (p < NTOK)
                    *(float2*)&g_v[((size_t)bhI*NTOK + p)*DH + e] = make_float2(a.x, a.y);
                if (p + 8 < NTOK)
                    *(float2*)&g_v[((size_t)bhI*NTOK + p + 8)*DH + e] = make_float2(a.z, a.w);
            } else {
                unsigned* dh = which ? g_kh : g_qh;
                unsigned* dl = which ? g_kl : g_ql;
                size_t base = (size_t)bhI * NTOKP * 16 + (e >> 1);
                if (p < NTOK) {
                    unsigned hw, lw; split2(a.x*s, a.y*s, hw, lw);
                    dh[base + (size_t)p*16] = hw; dl[base + (size_t)p*16] = lw;
                }
                if (p + 8 < NTOK) {
                    unsigned hw, lw; split2(a.z*s, a.w*s, hw, lw);
                    dh[base + (size_t)(p+8)*16] = hw; dl[base + (size_t)(p+8)*16] = lw;
                }
            }
        }
    }
}

// ============================================================
// Kernel 2: flash attention. cp.async double-buffered K/V tiles
// (pre-split), Q direct pre-split, P register-resident.
// ============================================================
__global__ __launch_bounds__(256) void attn_mma() {
    __shared__ __align__(16) unsigned Kh[2][64][20], Kl[2][64][20];
    __shared__ __align__(16) unsigned Vh[2][32][36], Vl[2][32][36];

    int tid = threadIdx.x;
    int wid = tid >> 5, lane = tid & 31;
    int r = lane >> 2, c = lane & 3;

    int q0 = blockIdx.x * 128;
    int bh = blockIdx.y;
    int h = bh & 7;

    int bRow = ((lane >> 4) << 3) | (lane & 7);
    int bSel = ((lane >> 3) & 1) * 4;

    int ckRow = tid >> 2, ckSeg = tid & 3;
    int cvRow = tid >> 3, cvSeg = tid & 7;
    size_t kSrc = ((size_t)bh * NTOKP + ckRow) * 16 + ckSeg * 4;
    size_t vSrc = ((size_t)bh * 32 + cvRow) * 320 + cvSeg * 4;

    auto copy_tile = [&](int jt, int buf) {
        cpa16(sptr(&Kh[buf][ckRow][ckSeg*4]), g_kh + kSrc + (size_t)jt*64*16);
        cpa16(sptr(&Kl[buf][ckRow][ckSeg*4]), g_kl + kSrc + (size_t)jt*64*16);
        cpa16(sptr(&Vh[buf][cvRow][cvSeg*4]), g_vth + vSrc + jt*32);
        cpa16(sptr(&Vl[buf][cvRow][cvSeg*4]), g_vtl + vSrc + jt*32);
    };

    // Q fragments: direct pre-split word loads
    unsigned qh[2][4], ql[2][4];
    {
        const unsigned* qbh = g_qh + (size_t)bh * NTOKP * 16;
        const unsigned* qbl = g_ql + (size_t)bh * NTOKP * 16;
        int pr = q0 + wid * 16 + r;
        #pragma unroll
        for (int kt = 0; kt < 2; kt++) {
            qh[kt][0] = qbh[(size_t)pr*16     + kt*8 + c];
            qh[kt][1] = qbh[(size_t)(pr+8)*16 + kt*8 + c];
            qh[kt][2] = qbh[(size_t)pr*16     + kt*8 + c + 4];
            qh[kt][3] = qbh[(size_t)(pr+8)*16 + kt*8 + c + 4];
            ql[kt][0] = qbl[(size_t)pr*16     + kt*8 + c];
            ql[kt][1] = qbl[(size_t)(pr+8)*16 + kt*8 + c];
            ql[kt][2] = qbl[(size_t)pr*16     + kt*8 + c + 4];
            ql[kt][3] = qbl[(size_t)(pr+8)*16 + kt*8 + c + 4];
        }
    }

    float4 O[4];
    #pragma unroll
    for (int i = 0; i < 4; i++) O[i] = make_float4(0,0,0,0);
    float m0 = -INFINITY, m1 = -INFINITY, l0 = 0.f, l1 = 0.f;

    copy_tile(0, 0);
    CP_COMMIT();
    int buf = 0;
    for (int jt = 0; jt < 10; jt++) {
        int j0 = jt * 64;
        CP_WAIT0();
        __syncthreads();
        if (jt < 9) { copy_tile(jt + 1, buf ^ 1); CP_COMMIT(); }

        unsigned KhB = sptr(Kh) + buf * 64*20*4;
        unsigned KlB = sptr(Kl) + buf * 64*20*4;
        unsigned VhB = sptr(Vh) + buf * 32*36*4;
        unsigned VlB = sptr(Vl) + buf * 32*36*4;

        // ---- S = Q K^T ----
        float4 acc[8];
        #pragma unroll
        for (int i = 0; i < 8; i++) acc[i] = make_float4(0,0,0,0);
        #pragma unroll
        for (int kt = 0; kt < 2; kt++) {
            #pragma unroll
            for (int ntp = 0; ntp < 4; ntp++) {
                unsigned off = ((ntp*16 + bRow) * 20 + kt*8 + bSel) * 4u;
                unsigned th[4], tl[4];
                ldsm4(th, KhB + off);
                ldsm4(tl, KlB + off);
                mma3(acc[2*ntp  ], qh[kt], ql[kt], th[0], th[1], tl[0], tl[1]);
                mma3(acc[2*ntp+1], qh[kt], ql[kt], th[2], th[3], tl[2], tl[3]);
            }
        }

        // ---- bias + tail mask ----
        {
            const float* bp = g_bias + ((size_t)(h * NPAD + q0 + wid*16 + r)) * NPAD + j0;
            #pragma unroll
            for (int nt = 0; nt < 8; nt++) {
                float2 b0v = *(const float2*)&bp[nt*8 + 2*c];
                float2 b1v = *(const float2*)&bp[8*NPAD + nt*8 + 2*c];
                acc[nt].x += b0v.x; acc[nt].y += b0v.y;
                acc[nt].z += b1v.x; acc[nt].w += b1v.y;
            }
            if (j0 + 64 > NTOK) {
                #pragma unroll
                for (int nt = 0; nt < 8; nt++) {
                    int jc = j0 + nt*8 + 2*c;
                    if (jc     >= NTOK) { acc[nt].x = -1e30f; acc[nt].z = -1e30f; }
                    if (jc + 1 >= NTOK) { acc[nt].y = -1e30f; acc[nt].w = -1e30f; }
                }
            }
        }

        // ---- online softmax (quad reduce) ----
        float t0 = -INFINITY, t1 = -INFINITY;
        #pragma unroll
        for (int nt = 0; nt < 8; nt++) {
            t0 = fmaxf(t0, fmaxf(acc[nt].x, acc[nt].y));
            t1 = fmaxf(t1, fmaxf(acc[nt].z, acc[nt].w));
        }
        #pragma unroll
        for (int off = 1; off <= 2; off <<= 1) {
            t0 = fmaxf(t0, __shfl_xor_sync(0xffffffffu, t0, off));
            t1 = fmaxf(t1, __shfl_xor_sync(0xffffffffu, t1, off));
        }
        float mn0 = fmaxf(m0, t0), mn1 = fmaxf(m1, t1);
        float cor0 = __expf(m0 - mn0), cor1 = __expf(m1 - mn1);
        float s0 = 0.f, s1 = 0.f;
        #pragma unroll
        for (int nt = 0; nt < 8; nt++) {
            acc[nt].x = __expf(acc[nt].x - mn0);
            acc[nt].y = __expf(acc[nt].y - mn0);
            acc[nt].z = __expf(acc[nt].z - mn1);
            acc[nt].w = __expf(acc[nt].w - mn1);
            s0 += acc[nt].x + acc[nt].y;
            s1 += acc[nt].z + acc[nt].w;
        }
        #pragma unroll
        for (int off = 1; off <= 2; off <<= 1) {
            s0 += __shfl_xor_sync(0xffffffffu, s0, off);
            s1 += __shfl_xor_sync(0xffffffffu, s1, off);
        }
        l0 = l0 * cor0 + s0;  m0 = mn0;
        l1 = l1 * cor1 + s1;  m1 = mn1;
        #pragma unroll
        for (int i = 0; i < 4; i++) {
            O[i].x *= cor0; O[i].y *= cor0;
            O[i].z *= cor1; O[i].w *= cor1;
        }

        // ---- O += P V ----
        #pragma unroll
        for (int kt = 0; kt < 4; kt++) {
            unsigned ph[4], pl[4];
            split2(acc[2*kt  ].x, acc[2*kt  ].y, ph[0], pl[0]);
            split2(acc[2*kt  ].z, acc[2*kt  ].w, ph[1], pl[1]);
            split2(acc[2*kt+1].x, acc[2*kt+1].y, ph[2], pl[2]);
            split2(acc[2*kt+1].z, acc[2*kt+1].w, ph[3], pl[3]);
            #pragma unroll
            for (int ntp = 0; ntp < 2; ntp++) {
                unsigned off = ((ntp*16 + bRow) * 36 + kt*8 + bSel) * 4u;
                unsigned th[4], tl[4];
                ldsm4(th, VhB + off);
                ldsm4(tl, VlB + off);
                mma3(O[2*ntp  ], ph, pl, th[0], th[1], tl[0], tl[1]);
                mma3(O[2*ntp+1], ph, pl, th[2], th[3], tl[2], tl[3]);
            }
        }
        buf ^= 1;
    }

    // epilogue: O pre-split to g_oh/g_ol (b, p, [word])
    float inv0 = 1.f / l0, inv1 = 1.f / l1;
    size_t ob = (size_t)(bh >> 3) * NTOKP * 128 + h * 16;
    #pragma unroll
    for (int nt = 0; nt < 4; nt++) {
        int w2 = nt * 4 + c;
        int p = q0 + wid * 16 + r;
        if (p < NTOK) {
            unsigned hw, lw; split2(O[nt].x * inv0, O[nt].y * inv0, hw, lw);
            g_oh[ob + (size_t)p*128 + w2] = hw;
            g_ol[ob + (size_t)p*128 + w2] = lw;
        }
        if (p + 8 < NTOK) {
            unsigned hw, lw; split2(O[nt].z * inv1, O[nt].w * inv1, hw, lw);
            g_oh[ob + (size_t)(p+8)*128 + w2] = hw;
            g_ol[ob + (size_t)(p+8)*128 + w2] = lw;
        }
    }
}

// ============================================================
// Kernel 3: output projection. Same pipeline as qkv; A from g_oh,
// B from g_woh. Transposed store via Cs union.
// ============================================================
__global__ __launch_bounds__(256) void out_mma(float* __restrict__ out) {
    extern __shared__ __align__(16) unsigned osm[];
    float (*Cs)[69] = (float(*)[69])osm;

    int b  = blockIdx.z;
    int p0 = blockIdx.x * 128;
    int n0 = blockIdx.y * 64;
    int tid = threadIdx.x;
    int wid = tid >> 5, lane = tid & 31;
    int wm = wid & 3, wn = wid >> 2;
    int r = lane >> 2, c = lane & 3;
    unsigned smb = sptr(osm);

    float4 acc[2][4];
    #pragma unroll
    for (int i = 0; i < 2; i++)
        #pragma unroll
        for (int j = 0; j < 4; j++) acc[i][j] = make_float4(0,0,0,0);

    int aRow = lane & 15;
    int aSel = (lane >> 4) * 4;
    int bRow = ((lane >> 4) << 3) | (lane & 7);
    int bSel = ((lane >> 3) & 1) * 4;

    int caRow = tid >> 1, caHalf = tid & 1;
    int cbRow = tid >> 2, cbSeg = tid & 3;
    size_t aSrc = ((size_t)b * NTOKP + p0 + caRow) * 128 + caHalf * 8;
    size_t bSrc = (size_t)(n0 + cbRow) * 128 + cbSeg * 4;

    auto copy_slab = [&](int slab, int buf) {
        unsigned sb = smb + buf * STG * 4;
        unsigned dA  = sb + (caRow*20 + caHalf*8) * 4;
        unsigned dAl = dA + 2560 * 4;
        const unsigned* sh = g_oh + aSrc + slab*16;
        const unsigned* sl = g_ol + aSrc + slab*16;
        cpa16(dA,       sh);  cpa16(dA  + 16, sh + 4);
        cpa16(dAl,      sl);  cpa16(dAl + 16, sl + 4);
        unsigned dB  = sb + (5120 + cbRow*20 + cbSeg*4) * 4;
        cpa16(dB,            g_woh + bSrc + slab*16);
        cpa16(dB + 1280*4,   g_wol + bSrc + slab*16);
    };

    copy_slab(0, 0);
    CP_COMMIT();
    int buf = 0;
    for (int s = 0; s < 8; s++) {
        CP_WAIT0();
        __syncthreads();
        if (s < 7) { copy_slab(s + 1, buf ^ 1); CP_COMMIT(); }

        unsigned AhB = smb + buf * STG * 4;
        unsigned AlB = AhB + 2560 * 4;
        unsigned BhB = AhB + 5120 * 4;
        unsigned BlB = AhB + 6400 * 4;
        #pragma unroll
        for (int ktl = 0; ktl < 2; ktl++) {
            unsigned ah[2][4], al[2][4];
            #pragma unroll
            for (int mt = 0; mt < 2; mt++) {
                unsigned off = ((wm*32 + mt*16 + aRow) * 20 + ktl*8 + aSel) * 4u;
                ldsm4(ah[mt], AhB + off);
                ldsm4(al[mt], AlB + off);
            }
            unsigned bhf[4][2], blf[4][2];
            #pragma unroll
            for (int ntp = 0; ntp < 2; ntp++) {
                unsigned off = ((wn*32 + ntp*16 + bRow) * 20 + ktl*8 + bSel) * 4u;
                unsigned t4[4];
                ldsm4(t4, BhB + off);
                bhf[2*ntp][0] = t4[0]; bhf[2*ntp][1] = t4[1];
                bhf[2*ntp+1][0] = t4[2]; bhf[2*ntp+1][1] = t4[3];
                ldsm4(t4, BlB + off);
                blf[2*ntp][0] = t4[0]; blf[2*ntp][1] = t4[1];
                blf[2*ntp+1][0] = t4[2]; blf[2*ntp+1][1] = t4[3];
            }
            #pragma unroll
            for (int nt = 0; nt < 4; nt++)
                #pragma unroll
                for (int mt = 0; mt < 2; mt++)
                    mma3(acc[mt][nt], ah[mt], al[mt],
                         bhf[nt][0], bhf[nt][1], blf[nt][0], blf[nt][1]);
        }
        buf ^= 1;
    }

    __syncthreads();   // staging done before Cs reuse

    #pragma unroll
    for (int mt = 0; mt < 2; mt++) {
        int m = wm * 32 + mt * 16 + r;
        #pragma unroll
        for (int nt = 0; nt < 4; nt++) {
            int n = wn * 32 + nt * 8 + 2 * c;
            Cs[m    ][n    ] = acc[mt][nt].x;
            Cs[m    ][n + 1] = acc[mt][nt].y;
            Cs[m + 8][n    ] = acc[mt][nt].z;
            Cs[m + 8][n + 1] = acc[mt][nt].w;
        }
    }
    __syncthreads();

    #pragma unroll
    for (int it = 0; it < 32; it++) {
        int idx = it * 256 + tid;
        int n = idx >> 7;
        int m = idx & 127;
        int p = p0 + m;
        if (p < NTOK)
            out[((size_t)b * DD + n0 + n) * NTOK + p] = Cs[m][n];
    }
}

// ============================================================
extern "C" void kernel_launch(void* const* d_in, const int* in_sizes, int n_in,
                              void* d_out, int out_size) {
    const float* x          = (const float*)d_in[0];
    const float* w_qkv      = (const float*)d_in[1];
    const float* w_out      = (const float*)d_in[2];
    const float* bias_table = (const float*)d_in[3];
    const int*   rel        = (const int*)d_in[4];
    float* out = (float*)d_out;

    cudaFuncSetAttribute(qkv_mma, cudaFuncAttributeMaxDynamicSharedMemorySize,
                         GEMM_SMEM);
    cudaFuncSetAttribute(out_mma, cudaFuncAttributeMaxDynamicSharedMemorySize,
                         GEMM_SMEM);

    bias_fill<<<(HEADS * NTOK * NTOK + 255) / 256, 256>>>(bias_table, rel);
    prep_w<<<512, 256>>>(w_qkv, w_out);
    prep_x<<<dim3(10, 4, BB), 256>>>(x);
    qkv_mma<<<dim3(5, 12, BB), 256, GEMM_SMEM>>>();
    prep_vt<<<dim3(10, NBH), 256>>>();
    attn_mma<<<dim3(5, NBH), 256>>>();
    out_mma<<<dim3(5, 4, BB), 256, GEMM_SMEM>>>(out);
}

// round 10
// speedup vs baseline: 1.0698x; 1.0000x over previous
#include <cuda_runtime.h>
#include <math.h>

#define BB    64
#define DD    256
#define HEADS 8
#define DH    32
#define NTOK  625
#define NTOKP 640
#define NPAD  640
#define NBH   (BB*HEADS)

// ---- scratch (device globals, zero-initialized) ----
__device__ __align__(128) unsigned g_xh[(size_t)BB*NTOKP*128];
__device__ __align__(128) unsigned g_xl[(size_t)BB*NTOKP*128];
__device__ __align__(128) unsigned g_wqh[768*128];
__device__ __align__(128) unsigned g_wql[768*128];
__device__ __align__(128) unsigned g_woh[256*128];
__device__ __align__(128) unsigned g_wol[256*128];
__device__ __align__(128) unsigned g_qh[(size_t)NBH*NTOKP*16];
__device__ __align__(128) unsigned g_ql[(size_t)NBH*NTOKP*16];
__device__ __align__(128) unsigned g_kh[(size_t)NBH*NTOKP*16];
__device__ __align__(128) unsigned g_kl[(size_t)NBH*NTOKP*16];
__device__ __align__(128) float    g_v [(size_t)NBH*NTOK*DH];
__device__ __align__(128) unsigned g_vth[(size_t)NBH*32*320];
__device__ __align__(128) unsigned g_vtl[(size_t)NBH*32*320];
__device__ __align__(128) unsigned g_oh[(size_t)BB*NTOKP*128];
__device__ __align__(128) unsigned g_ol[(size_t)BB*NTOKP*128];
__device__ __align__(16)  float    g_bias[HEADS*NPAD*NPAD];

// ================= bf16 split helpers =================
__device__ __forceinline__ unsigned packbf(float x0, float x1) {
    unsigned u;
    asm("cvt.rn.bf16x2.f32 %0, %1, %2;" : "=r"(u) : "f"(x1), "f"(x0));
    return u;
}
__device__ __forceinline__ void split2(float x0, float x1,
                                       unsigned &h, unsigned &l) {
    h = packbf(x0, x1);
    float h0 = __uint_as_float(h << 16);
    float h1 = __uint_as_float(h & 0xffff0000u);
    l = packbf(x0 - h0, x1 - h1);
}
__device__ __forceinline__ void mma16(float4 &d, const unsigned a[4],
                                      unsigned b0, unsigned b1) {
    asm volatile(
        "mma.sync.aligned.m16n8k16.row.col.f32.bf16.bf16.f32 "
        "{%0,%1,%2,%3}, {%4,%5,%6,%7}, {%8,%9}, {%0,%1,%2,%3};"
        : "+f"(d.x), "+f"(d.y), "+f"(d.z), "+f"(d.w)
        : "r"(a[0]), "r"(a[1]), "r"(a[2]), "r"(a[3]), "r"(b0), "r"(b1));
}
__device__ __forceinline__ void mma3(float4 &d, const unsigned ah[4],
                                     const unsigned al[4],
                                     unsigned bh0, unsigned bh1,
                                     unsigned bl0, unsigned bl1) {
    mma16(d, ah, bh0, bh1);
    mma16(d, ah, bl0, bl1);
    mma16(d, al, bh0, bh1);
}
// ================= ldmatrix / cp.async helpers =================
__device__ __forceinline__ unsigned sptr(const void* p) {
    return (unsigned)__cvta_generic_to_shared(p);
}
__device__ __forceinline__ void ldsm4(unsigned r[4], unsigned addr) {
    asm volatile("ldmatrix.sync.aligned.m8n8.x4.shared.b16 {%0,%1,%2,%3}, [%4];"
        : "=r"(r[0]), "=r"(r[1]), "=r"(r[2]), "=r"(r[3]) : "r"(addr));
}
__device__ __forceinline__ void cpa16(unsigned dst, const void* src) {
    asm volatile("cp.async.cg.shared.global [%0], [%1], 16;" :: "r"(dst), "l"(src));
}
#define CP_COMMIT() asm volatile("cp.async.commit_group;")
#define CP_WAIT0()  asm volatile("cp.async.wait_group 0;")

// ============================================================
// Kernel 0: bias_fill
// ============================================================
__global__ void bias_fill(const float* __restrict__ table,
                          const int*   __restrict__ rel) {
    int idx = blockIdx.x * blockDim.x + threadIdx.x;
    const int total = HEADS * NTOK * NTOK;
    if (idx >= total) return;
    int h = idx / (NTOK * NTOK);
    int r = idx - h * (NTOK * NTOK);
    int i = r / NTOK;
    int j = r - i * NTOK;
    g_bias[(h * NPAD + i) * NPAD + j] = table[rel[r] * HEADS + h];
}

// ============================================================
// prep_w: split weights once into [n][k2-word] layouts
// ============================================================
__global__ void prep_w(const float* __restrict__ wq,
                       const float* __restrict__ wo) {
    int idx = blockIdx.x * 256 + threadIdx.x;
    if (idx < 768 * 128) {
        int k2 = idx / 768, n = idx - k2 * 768;
        split2(wq[(size_t)(2*k2) * 768 + n], wq[(size_t)(2*k2+1) * 768 + n],
               g_wqh[n*128 + k2], g_wql[n*128 + k2]);
    } else {
        int j = idx - 768 * 128;
        if (j < 256 * 128) {
            int k2 = j / 256, n = j - k2 * 256;
            split2(wo[(size_t)(2*k2) * 256 + n], wo[(size_t)(2*k2+1) * 256 + n],
                   g_woh[n*128 + k2], g_wol[n*128 + k2]);
        }
    }
}

// ============================================================
// prep_x: transpose+split x (b,k,p) -> word layout (b,p,[k2])
// ============================================================
__global__ __launch_bounds__(256) void prep_x(const float* __restrict__ x) {
    __shared__ float sm[64][65];
    int p0 = blockIdx.x * 64, k0 = blockIdx.y * 64, b = blockIdx.z;
    int t = threadIdx.x;
    int pp = t & 63, kk0 = t >> 6;
    const float* xb = x + ((size_t)b * DD + k0) * NTOK + p0;
    bool pok = (p0 + pp) < NTOK;
    #pragma unroll
    for (int i = 0; i < 16; i++) {
        int kk = kk0 + i * 4;
        sm[kk][pp] = pok ? xb[(size_t)kk * NTOK + pp] : 0.f;
    }
    __syncthreads();
    int row = t >> 2, wseg = t & 3;
    unsigned hw[8], lw[8];
    #pragma unroll
    for (int i = 0; i < 8; i++) {
        int j2 = wseg * 8 + i;
        split2(sm[2*j2][row], sm[2*j2+1][row], hw[i], lw[i]);
    }
    size_t base = ((size_t)b * NTOKP + p0 + row) * 128 + k0/2 + wseg*8;
    *(uint4*)&g_xh[base]     = *(uint4*)&hw[0];
    *(uint4*)&g_xh[base + 4] = *(uint4*)&hw[4];
    *(uint4*)&g_xl[base]     = *(uint4*)&lw[0];
    *(uint4*)&g_xl[base + 4] = *(uint4*)&lw[4];
}

// ============================================================
// prep_vt: transpose+split V (bh,j,e) -> word layout (bh,e,[j2])
// (zero tail rows j >= NTOK).  FIX R8: row stride 36 (144B, 16B
// multiple) so the float4 staging stores are aligned.
// ============================================================
__global__ __launch_bounds__(256) void prep_vt() {
    __shared__ float sm[64][36];
    int jt = blockIdx.x, bh = blockIdx.y;
    int j0 = jt * 64, t = threadIdx.x;
    int j = t >> 2, e0 = (t & 3) * 8;
    const float* vb = g_v + (size_t)bh * NTOK * DH;
    if (j0 + j < NTOK) {
        *(float4*)&sm[j][e0]     = *(const float4*)&vb[(size_t)(j0+j) * DH + e0];
        *(float4*)&sm[j][e0 + 4] = *(const float4*)&vb[(size_t)(j0+j) * DH + e0 + 4];
    } else {
        #pragma unroll
        for (int i = 0; i < 8; i++) sm[j][e0 + i] = 0.f;
    }
    __syncthreads();
    int e = t >> 3, wseg = t & 7;
    unsigned hw[4], lw[4];
    #pragma unroll
    for (int i = 0; i < 4; i++) {
        int j2 = wseg * 4 + i;
        split2(sm[2*j2][e], sm[2*j2+1][e], hw[i], lw[i]);
    }
    size_t base = ((size_t)bh * 32 + e) * 320 + jt*32 + wseg*4;
    *(uint4*)&g_vth[base] = *(uint4*)hw;
    *(uint4*)&g_vtl[base] = *(uint4*)lw;
}

// ============================================================
// Kernel 1: QKV projection. cp.async double-buffered staging,
// LDSM fragments, bf16 3-mma. 128x64 tile, K=256, 8 slabs of 32.
// Stage layout (words): Ah[128][20] Al Bh[64][20] Bl = 7680/stage.
// ============================================================
#define STG 7680
#define GEMM_SMEM (2*STG*4)   // 61440 B

__global__ __launch_bounds__(256) void qkv_mma() {
    extern __shared__ __align__(16) unsigned qsm[];
    int b  = blockIdx.z;
    int p0 = blockIdx.x * 128;
    int n0 = blockIdx.y * 64;
    int tid = threadIdx.x;
    int wid = tid >> 5, lane = tid & 31;
    int wm = wid & 3, wn = wid >> 2;
    int r = lane >> 2, c = lane & 3;
    unsigned smb = sptr(qsm);

    float4 acc[2][4];
    #pragma unroll
    for (int i = 0; i < 2; i++)
        #pragma unroll
        for (int j = 0; j < 4; j++) acc[i][j] = make_float4(0,0,0,0);

    int aRow = lane & 15;
    int aSel = (lane >> 4) * 4;
    int bRow = ((lane >> 4) << 3) | (lane & 7);
    int bSel = ((lane >> 3) & 1) * 4;

    int caRow = tid >> 1, caHalf = tid & 1;
    int cbRow = tid >> 2, cbSeg = tid & 3;
    size_t aSrc = ((size_t)b * NTOKP + p0 + caRow) * 128 + caHalf * 8;
    size_t bSrc = (size_t)(n0 + cbRow) * 128 + cbSeg * 4;

    auto copy_slab = [&](int slab, int buf) {
        unsigned sb = smb + buf * STG * 4;
        unsigned dA  = sb + (caRow*20 + caHalf*8) * 4;
        unsigned dAl = dA + 2560 * 4;
        const unsigned* sh = g_xh + aSrc + slab*16;
        const unsigned* sl = g_xl + aSrc + slab*16;
        cpa16(dA,       sh);  cpa16(dA  + 16, sh + 4);
        cpa16(dAl,      sl);  cpa16(dAl + 16, sl + 4);
        unsigned dB  = sb + (5120 + cbRow*20 + cbSeg*4) * 4;
        cpa16(dB,            g_wqh + bSrc + slab*16);
        cpa16(dB + 1280*4,   g_wql + bSrc + slab*16);
    };

    copy_slab(0, 0);
    CP_COMMIT();
    int buf = 0;
    for (int s = 0; s < 8; s++) {
        CP_WAIT0();
        __syncthreads();
        if (s < 7) { copy_slab(s + 1, buf ^ 1); CP_COMMIT(); }

        unsigned AhB = smb + buf * STG * 4;
        unsigned AlB = AhB + 2560 * 4;
        unsigned BhB = AhB + 5120 * 4;
        unsigned BlB = AhB + 6400 * 4;
        #pragma unroll
        for (int ktl = 0; ktl < 2; ktl++) {
            unsigned ah[2][4], al[2][4];
            #pragma unroll
            for (int mt = 0; mt < 2; mt++) {
                unsigned off = ((wm*32 + mt*16 + aRow) * 20 + ktl*8 + aSel) * 4u;
                ldsm4(ah[mt], AhB + off);
                ldsm4(al[mt], AlB + off);
            }
            unsigned bhf[4][2], blf[4][2];
            #pragma unroll
            for (int ntp = 0; ntp < 2; ntp++) {
                unsigned off = ((wn*32 + ntp*16 + bRow) * 20 + ktl*8 + bSel) * 4u;
                unsigned t4[4];
                ldsm4(t4, BhB + off);
                bhf[2*ntp][0] = t4[0]; bhf[2*ntp][1] = t4[1];
                bhf[2*ntp+1][0] = t4[2]; bhf[2*ntp+1][1] = t4[3];
                ldsm4(t4, BlB + off);
                blf[2*ntp][0] = t4[0]; blf[2*ntp][1] = t4[1];
                blf[2*ntp+1][0] = t4[2]; blf[2*ntp+1][1] = t4[3];
            }
            #pragma unroll
            for (int nt = 0; nt < 4; nt++)
                #pragma unroll
                for (int mt = 0; mt < 2; mt++)
                    mma3(acc[mt][nt], ah[mt], al[mt],
                         bhf[nt][0], bhf[nt][1], blf[nt][0], blf[nt][1]);
        }
        buf ^= 1;
    }

    // epilogue: q/k pre-split words; v fp32
    #pragma unroll
    for (int nt = 0; nt < 4; nt++) {
        int ng0 = n0 + wn * 32 + nt * 8 + 2 * c;
        int which = ng0 >> 8;
        int h = (ng0 >> 5) & 7;
        int e = ng0 & 31;
        int bhI = b * HEADS + h;
        float s = (which == 0) ? 0.17677669529663687f : 1.f;
        #pragma unroll
        for (int mt = 0; mt < 2; mt++) {
            int p = p0 + wm * 32 + mt * 16 + r;
            float4 a = acc[mt][nt];
            if (which == 2) {
                if (p < NTOK)
                    *(float2*)&g_v[((size_t)bhI*NTOK + p)*DH + e] = make_float2(a.x, a.y);
                if (p + 8 < NTOK)
                    *(float2*)&g_v[((size_t)bhI*NTOK + p + 8)*DH + e] = make_float2(a.z, a.w);
            } else {
                unsigned* dh = which ? g_kh : g_qh;
                unsigned* dl = which ? g_kl : g_ql;
                size_t base = (size_t)bhI * NTOKP * 16 + (e >> 1);
                if (p < NTOK) {
                    unsigned hw, lw; split2(a.x*s, a.y*s, hw, lw);
                    dh[base + (size_t)p*16] = hw; dl[base + (size_t)p*16] = lw;
                }
                if (p + 8 < NTOK) {
                    unsigned hw, lw; split2(a.z*s, a.w*s, hw, lw);
                    dh[base + (size_t)(p+8)*16] = hw; dl[base + (size_t)(p+8)*16] = lw;
                }
            }
        }
    }
}

// ============================================================
// Kernel 2: flash attention. cp.async double-buffered K/V tiles
// (pre-split), Q direct pre-split, P register-resident.
// ============================================================
__global__ __launch_bounds__(256) void attn_mma() {
    __shared__ __align__(16) unsigned Kh[2][64][20], Kl[2][64][20];
    __shared__ __align__(16) unsigned Vh[2][32][36], Vl[2][32][36];

    int tid = threadIdx.x;
    int wid = tid >> 5, lane = tid & 31;
    int r = lane >> 2, c = lane & 3;

    int q0 = blockIdx.x * 128;
    int bh = blockIdx.y;
    int h = bh & 7;

    int bRow = ((lane >> 4) << 3) | (lane & 7);
    int bSel = ((lane >> 3) & 1) * 4;

    int ckRow = tid >> 2, ckSeg = tid & 3;
    int cvRow = tid >> 3, cvSeg = tid & 7;
    size_t kSrc = ((size_t)bh * NTOKP + ckRow) * 16 + ckSeg * 4;
    size_t vSrc = ((size_t)bh * 32 + cvRow) * 320 + cvSeg * 4;

    auto copy_tile = [&](int jt, int buf) {
        cpa16(sptr(&Kh[buf][ckRow][ckSeg*4]), g_kh + kSrc + (size_t)jt*64*16);
        cpa16(sptr(&Kl[buf][ckRow][ckSeg*4]), g_kl + kSrc + (size_t)jt*64*16);
        cpa16(sptr(&Vh[buf][cvRow][cvSeg*4]), g_vth + vSrc + jt*32);
        cpa16(sptr(&Vl[buf][cvRow][cvSeg*4]), g_vtl + vSrc + jt*32);
    };

    // Q fragments: direct pre-split word loads
    unsigned qh[2][4], ql[2][4];
    {
        const unsigned* qbh = g_qh + (size_t)bh * NTOKP * 16;
        const unsigned* qbl = g_ql + (size_t)bh * NTOKP * 16;
        int pr = q0 + wid * 16 + r;
        #pragma unroll
        for (int kt = 0; kt < 2; kt++) {
            qh[kt][0] = qbh[(size_t)pr*16     + kt*8 + c];
            qh[kt][1] = qbh[(size_t)(pr+8)*16 + kt*8 + c];
            qh[kt][2] = qbh[(size_t)pr*16     + kt*8 + c + 4];
            qh[kt][3] = qbh[(size_t)(pr+8)*16 + kt*8 + c + 4];
            ql[kt][0] = qbl[(size_t)pr*16     + kt*8 + c];
            ql[kt][1] = qbl[(size_t)(pr+8)*16 + kt*8 + c];
            ql[kt][2] = qbl[(size_t)pr*16     + kt*8 + c + 4];
            ql[kt][3] = qbl[(size_t)(pr+8)*16 + kt*8 + c + 4];
        }
    }

    float4 O[4];
    #pragma unroll
    for (int i = 0; i < 4; i++) O[i] = make_float4(0,0,0,0);
    float m0 = -INFINITY, m1 = -INFINITY, l0 = 0.f, l1 = 0.f;

    copy_tile(0, 0);
    CP_COMMIT();
    int buf = 0;
    for (int jt = 0; jt < 10; jt++) {
        int j0 = jt * 64;
        CP_WAIT0();
        __syncthreads();
        if (jt < 9) { copy_tile(jt + 1, buf ^ 1); CP_COMMIT(); }

        unsigned KhB = sptr(Kh) + buf * 64*20*4;
        unsigned KlB = sptr(Kl) + buf * 64*20*4;
        unsigned VhB = sptr(Vh) + buf * 32*36*4;
        unsigned VlB = sptr(Vl) + buf * 32*36*4;

        // ---- S = Q K^T ----
        float4 acc[8];
        #pragma unroll
        for (int i = 0; i < 8; i++) acc[i] = make_float4(0,0,0,0);
        #pragma unroll
        for (int kt = 0; kt < 2; kt++) {
            #pragma unroll
            for (int ntp = 0; ntp < 4; ntp++) {
                unsigned off = ((ntp*16 + bRow) * 20 + kt*8 + bSel) * 4u;
                unsigned th[4], tl[4];
                ldsm4(th, KhB + off);
                ldsm4(tl, KlB + off);
                mma3(acc[2*ntp  ], qh[kt], ql[kt], th[0], th[1], tl[0], tl[1]);
                mma3(acc[2*ntp+1], qh[kt], ql[kt], th[2], th[3], tl[2], tl[3]);
            }
        }

        // ---- bias + tail mask ----
        {
            const float* bp = g_bias + ((size_t)(h * NPAD + q0 + wid*16 + r)) * NPAD + j0;
            #pragma unroll
            for (int nt = 0; nt < 8; nt++) {
                float2 b0v = *(const float2*)&bp[nt*8 + 2*c];
                float2 b1v = *(const float2*)&bp[8*NPAD + nt*8 + 2*c];
                acc[nt].x += b0v.x; acc[nt].y += b0v.y;
                acc[nt].z += b1v.x; acc[nt].w += b1v.y;
            }
            if (j0 + 64 > NTOK) {
                #pragma unroll
                for (int nt = 0; nt < 8; nt++) {
                    int jc = j0 + nt*8 + 2*c;
                    if (jc     >= NTOK) { acc[nt].x = -1e30f; acc[nt].z = -1e30f; }
                    if (jc + 1 >= NTOK) { acc[nt].y = -1e30f; acc[nt].w = -1e30f; }
                }
            }
        }

        // ---- online softmax (quad reduce) ----
        float t0 = -INFINITY, t1 = -INFINITY;
        #pragma unroll
        for (int nt = 0; nt < 8; nt++) {
            t0 = fmaxf(t0, fmaxf(acc[nt].x, acc[nt].y));
            t1 = fmaxf(t1, fmaxf(acc[nt].z, acc[nt].w));
        }
        #pragma unroll
        for (int off = 1; off <= 2; off <<= 1) {
            t0 = fmaxf(t0, __shfl_xor_sync(0xffffffffu, t0, off));
            t1 = fmaxf(t1, __shfl_xor_sync(0xffffffffu, t1, off));
        }
        float mn0 = fmaxf(m0, t0), mn1 = fmaxf(m1, t1);
        float cor0 = __expf(m0 - mn0), cor1 = __expf(m1 - mn1);
        float s0 = 0.f, s1 = 0.f;
        #pragma unroll
        for (int nt = 0; nt < 8; nt++) {
            acc[nt].x = __expf(acc[nt].x - mn0);
            acc[nt].y = __expf(acc[nt].y - mn0);
            acc[nt].z = __expf(acc[nt].z - mn1);
            acc[nt].w = __expf(acc[nt].w - mn1);
            s0 += acc[nt].x + acc[nt].y;
            s1 += acc[nt].z + acc[nt].w;
        }
        #pragma unroll
        for (int off = 1; off <= 2; off <<= 1) {
            s0 += __shfl_xor_sync(0xffffffffu, s0, off);
            s1 += __shfl_xor_sync(0xffffffffu, s1, off);
        }
        l0 = l0 * cor0 + s0;  m0 = mn0;
        l1 = l1 * cor1 + s1;  m1 = mn1;
        #pragma unroll
        for (int i = 0; i < 4; i++) {
            O[i].x *= cor0; O[i].y *= cor0;
            O[i].z *= cor1; O[i].w *= cor1;
        }

        // ---- O += P V ----
        #pragma unroll
        for (int kt = 0; kt < 4; kt++) {
            unsigned ph[4], pl[4];
            split2(acc[2*kt  ].x, acc[2*kt  ].y, ph[0], pl[0]);
            split2(acc[2*kt  ].z, acc[2*kt  ].w, ph[1], pl[1]);
            split2(acc[2*kt+1].x, acc[2*kt+1].y, ph[2], pl[2]);
            split2(acc[2*kt+1].z, acc[2*kt+1].w, ph[3], pl[3]);
            #pragma unroll
            for (int ntp = 0; ntp < 2; ntp++) {
                unsigned off = ((ntp*16 + bRow) * 36 + kt*8 + bSel) * 4u;
                unsigned th[4], tl[4];
                ldsm4(th, VhB + off);
                ldsm4(tl, VlB + off);
                mma3(O[2*ntp  ], ph, pl, th[0], th[1], tl[0], tl[1]);
                mma3(O[2*ntp+1], ph, pl, th[2], th[3], tl[2], tl[3]);
            }
        }
        buf ^= 1;
    }

    // epilogue: O pre-split to g_oh/g_ol (b, p, [word])
    float inv0 = 1.f / l0, inv1 = 1.f / l1;
    size_t ob = (size_t)(bh >> 3) * NTOKP * 128 + h * 16;
    #pragma unroll
    for (int nt = 0; nt < 4; nt++) {
        int w2 = nt * 4 + c;
        int p = q0 + wid * 16 + r;
        if (p < NTOK) {
            unsigned hw, lw; split2(O[nt].x * inv0, O[nt].y * inv0, hw, lw);
            g_oh[ob + (size_t)p*128 + w2] = hw;
            g_ol[ob + (size_t)p*128 + w2] = lw;
        }
        if (p + 8 < NTOK) {
            unsigned hw, lw; split2(O[nt].z * inv1, O[nt].w * inv1, hw, lw);
            g_oh[ob + (size_t)(p+8)*128 + w2] = hw;
            g_ol[ob + (size_t)(p+8)*128 + w2] = lw;
        }
    }
}

// ============================================================
// Kernel 3: output projection. Same pipeline as qkv; A from g_oh,
// B from g_woh. Transposed store via Cs union.
// ============================================================
__global__ __launch_bounds__(256) void out_mma(float* __restrict__ out) {
    extern __shared__ __align__(16) unsigned osm[];
    float (*Cs)[69] = (float(*)[69])osm;

    int b  = blockIdx.z;
    int p0 = blockIdx.x * 128;
    int n0 = blockIdx.y * 64;
    int tid = threadIdx.x;
    int wid = tid >> 5, lane = tid & 31;
    int wm = wid & 3, wn = wid >> 2;
    int r = lane >> 2, c = lane & 3;
    unsigned smb = sptr(osm);

    float4 acc[2][4];
    #pragma unroll
    for (int i = 0; i < 2; i++)
        #pragma unroll
        for (int j = 0; j < 4; j++) acc[i][j] = make_float4(0,0,0,0);

    int aRow = lane & 15;
    int aSel = (lane >> 4) * 4;
    int bRow = ((lane >> 4) << 3) | (lane & 7);
    int bSel = ((lane >> 3) & 1) * 4;

    int caRow = tid >> 1, caHalf = tid & 1;
    int cbRow = tid >> 2, cbSeg = tid & 3;
    size_t aSrc = ((size_t)b * NTOKP + p0 + caRow) * 128 + caHalf * 8;
    size_t bSrc = (size_t)(n0 + cbRow) * 128 + cbSeg * 4;

    auto copy_slab = [&](int slab, int buf) {
        unsigned sb = smb + buf * STG * 4;
        unsigned dA  = sb + (caRow*20 + caHalf*8) * 4;
        unsigned dAl = dA + 2560 * 4;
        const unsigned* sh = g_oh + aSrc + slab*16;
        const unsigned* sl = g_ol + aSrc + slab*16;
        cpa16(dA,       sh);  cpa16(dA  + 16, sh + 4);
        cpa16(dAl,      sl);  cpa16(dAl + 16, sl + 4);
        unsigned dB  = sb + (5120 + cbRow*20 + cbSeg*4) * 4;
        cpa16(dB,            g_woh + bSrc + slab*16);
        cpa16(dB + 1280*4,   g_wol + bSrc + slab*16);
    };

    copy_slab(0, 0);
    CP_COMMIT();
    int buf = 0;
    for (int s = 0; s < 8; s++) {
        CP_WAIT0();
        __syncthreads();
        if (s < 7) { copy_slab(s + 1, buf ^ 1); CP_COMMIT(); }

        unsigned AhB = smb + buf * STG * 4;
        unsigned AlB = AhB + 2560 * 4;
        unsigned BhB = AhB + 5120 * 4;
        unsigned BlB = AhB + 6400 * 4;
        #pragma unroll
        for (int ktl = 0; ktl < 2; ktl++) {
            unsigned ah[2][4], al[2][4];
            #pragma unroll
            for (int mt = 0; mt < 2; mt++) {
                unsigned off = ((wm*32 + mt*16 + aRow) * 20 + ktl*8 + aSel) * 4u;
                ldsm4(ah[mt], AhB + off);
                ldsm4(al[mt], AlB + off);
            }
            unsigned bhf[4][2], blf[4][2];
            #pragma unroll
            for (int ntp = 0; ntp < 2; ntp++) {
                unsigned off = ((wn*32 + ntp*16 + bRow) * 20 + ktl*8 + bSel) * 4u;
                unsigned t4[4];
                ldsm4(t4, BhB + off);
                bhf[2*ntp][0] = t4[0]; bhf[2*ntp][1] = t4[1];
                bhf[2*ntp+1][0] = t4[2]; bhf[2*ntp+1][1] = t4[3];
                ldsm4(t4, BlB + off);
                blf[2*ntp][0] = t4[0]; blf[2*ntp][1] = t4[1];
                blf[2*ntp+1][0] = t4[2]; blf[2*ntp+1][1] = t4[3];
            }
            #pragma unroll
            for (int nt = 0; nt < 4; nt++)
                #pragma unroll
                for (int mt = 0; mt < 2; mt++)
                    mma3(acc[mt][nt], ah[mt], al[mt],
                         bhf[nt][0], bhf[nt][1], blf[nt][0], blf[nt][1]);
        }
        buf ^= 1;
    }

    __syncthreads();   // staging done before Cs reuse

    #pragma unroll
    for (int mt = 0; mt < 2; mt++) {
        int m = wm * 32 + mt * 16 + r;
        #pragma unroll
        for (int nt = 0; nt < 4; nt++) {
            int n = wn * 32 + nt * 8 + 2 * c;
            Cs[m    ][n    ] = acc[mt][nt].x;
            Cs[m    ][n + 1] = acc[mt][nt].y;
            Cs[m + 8][n    ] = acc[mt][nt].z;
            Cs[m + 8][n + 1] = acc[mt][nt].w;
        }
    }
    __syncthreads();

    #pragma unroll
    for (int it = 0; it < 32; it++) {
        int idx = it * 256 + tid;
        int n = idx >> 7;
        int m = idx & 127;
        int p = p0 + m;
        if (p < NTOK)
            out[((size_t)b * DD + n0 + n) * NTOK + p] = Cs[m][n];
    }
}

// ============================================================
extern "C" void kernel_launch(void* const* d_in, const int* in_sizes, int n_in,
                              void* d_out, int out_size) {
    const float* x          = (const float*)d_in[0];
    const float* w_qkv      = (const float*)d_in[1];
    const float* w_out      = (const float*)d_in[2];
    const float* bias_table = (const float*)d_in[3];
    const int*   rel        = (const int*)d_in[4];
    float* out = (float*)d_out;

    cudaFuncSetAttribute(qkv_mma, cudaFuncAttributeMaxDynamicSharedMemorySize,
                         GEMM_SMEM);
    cudaFuncSetAttribute(out_mma, cudaFuncAttributeMaxDynamicSharedMemorySize,
                         GEMM_SMEM);

    bias_fill<<<(HEADS * NTOK * NTOK + 255) / 256, 256>>>(bias_table, rel);
    prep_w<<<512, 256>>>(w_qkv, w_out);
    prep_x<<<dim3(10, 4, BB), 256>>>(x);
    qkv_mma<<<dim3(5, 12, BB), 256, GEMM_SMEM>>>();
    prep_vt<<<dim3(10, NBH), 256>>>();
    attn_mma<<<dim3(5, NBH), 256>>>();
    out_mma<<<dim3(5, 4, BB), 256, GEMM_SMEM>>>(out);
}

// round 11
// speedup vs baseline: 1.4838x; 1.3869x over previous
#include <cuda_runtime.h>
#include <cuda_fp16.h>
#include <math.h>

#define BB    64
#define DD    256
#define HEADS 8
#define DH    32
#define NTOK  625
#define NTOKP 640
#define NPAD  640
#define NBH   (BB*HEADS)

// ---- scratch (device globals, zero-initialized) ----
__device__ __align__(128) unsigned g_xh[(size_t)BB*NTOKP*128];   // x single fp16 words
__device__ __align__(128) unsigned g_wqh[768*128];               // w_qkv hi
__device__ __align__(128) unsigned g_wql[768*128];               // w_qkv lo
__device__ __align__(128) unsigned g_woh[256*128];               // w_out single
__device__ __align__(128) unsigned g_qh[(size_t)NBH*NTOKP*16];   // Q hi
__device__ __align__(128) unsigned g_ql[(size_t)NBH*NTOKP*16];   // Q lo
__device__ __align__(128) unsigned g_kh[(size_t)NBH*NTOKP*16];   // K single
__device__ __align__(128) float    g_v [(size_t)NBH*NTOK*DH];
__device__ __align__(128) unsigned g_vth[(size_t)NBH*32*320];    // V^T hi
__device__ __align__(128) unsigned g_vtl[(size_t)NBH*32*320];    // V^T lo
__device__ __align__(128) unsigned g_oh[(size_t)BB*NTOKP*128];   // O hi
__device__ __align__(128) unsigned g_ol[(size_t)BB*NTOKP*128];   // O lo
__device__ __align__(16)  float    g_bias[HEADS*NPAD*NPAD];

// ================= fp16 pack/split helpers =================
__device__ __forceinline__ unsigned packhf(float x0, float x1) {
    unsigned u;
    asm("cvt.rn.f16x2.f32 %0, %1, %2;" : "=r"(u) : "f"(x1), "f"(x0));
    return u;
}
__device__ __forceinline__ void splith2(float x0, float x1,
                                        unsigned &h, unsigned &l) {
    h = packhf(x0, x1);
    __half2 hh = *reinterpret_cast<__half2*>(&h);
    l = packhf(x0 - __low2float(hh), x1 - __high2float(hh));
}
__device__ __forceinline__ void mma16(float4 &d, const unsigned a[4],
                                      unsigned b0, unsigned b1) {
    asm volatile(
        "mma.sync.aligned.m16n8k16.row.col.f32.f16.f16.f32 "
        "{%0,%1,%2,%3}, {%4,%5,%6,%7}, {%8,%9}, {%0,%1,%2,%3};"
        : "+f"(d.x), "+f"(d.y), "+f"(d.z), "+f"(d.w)
        : "r"(a[0]), "r"(a[1]), "r"(a[2]), "r"(a[3]), "r"(b0), "r"(b1));
}
// ================= ldmatrix / cp.async helpers =================
__device__ __forceinline__ unsigned sptr(const void* p) {
    return (unsigned)__cvta_generic_to_shared(p);
}
__device__ __forceinline__ void ldsm4(unsigned r[4], unsigned addr) {
    asm volatile("ldmatrix.sync.aligned.m8n8.x4.shared.b16 {%0,%1,%2,%3}, [%4];"
        : "=r"(r[0]), "=r"(r[1]), "=r"(r[2]), "=r"(r[3]) : "r"(addr));
}
__device__ __forceinline__ void cpa16(unsigned dst, const void* src) {
    asm volatile("cp.async.cg.shared.global [%0], [%1], 16;" :: "r"(dst), "l"(src));
}
#define CP_COMMIT() asm volatile("cp.async.commit_group;")
#define CP_WAIT0()  asm volatile("cp.async.wait_group 0;")

// ============================================================
// Kernel 0: bias_fill
// ============================================================
__global__ void bias_fill(const float* __restrict__ table,
                          const int*   __restrict__ rel) {
    int idx = blockIdx.x * blockDim.x + threadIdx.x;
    const int total = HEADS * NTOK * NTOK;
    if (idx >= total) return;
    int h = idx / (NTOK * NTOK);
    int r = idx - h * (NTOK * NTOK);
    int i = r / NTOK;
    int j = r - i * NTOK;
    g_bias[(h * NPAD + i) * NPAD + j] = table[rel[r] * HEADS + h];
}

// ============================================================
// prep_w: w_qkv split (h+l), w_out single fp16
// ============================================================
__global__ void prep_w(const float* __restrict__ wq,
                       const float* __restrict__ wo) {
    int idx = blockIdx.x * 256 + threadIdx.x;
    if (idx < 768 * 128) {
        int k2 = idx / 768, n = idx - k2 * 768;
        splith2(wq[(size_t)(2*k2) * 768 + n], wq[(size_t)(2*k2+1) * 768 + n],
                g_wqh[n*128 + k2], g_wql[n*128 + k2]);
    } else {
        int j = idx - 768 * 128;
        if (j < 256 * 128) {
            int k2 = j / 256, n = j - k2 * 256;
            g_woh[n*128 + k2] = packhf(wo[(size_t)(2*k2) * 256 + n],
                                       wo[(size_t)(2*k2+1) * 256 + n]);
        }
    }
}

// ============================================================
// prep_x: transpose x (b,k,p) -> single fp16 words (b,p,[k2])
// ============================================================
__global__ __launch_bounds__(256) void prep_x(const float* __restrict__ x) {
    __shared__ float sm[64][65];
    int p0 = blockIdx.x * 64, k0 = blockIdx.y * 64, b = blockIdx.z;
    int t = threadIdx.x;
    int pp = t & 63, kk0 = t >> 6;
    const float* xb = x + ((size_t)b * DD + k0) * NTOK + p0;
    bool pok = (p0 + pp) < NTOK;
    #pragma unroll
    for (int i = 0; i < 16; i++) {
        int kk = kk0 + i * 4;
        sm[kk][pp] = pok ? xb[(size_t)kk * NTOK + pp] : 0.f;
    }
    __syncthreads();
    int row = t >> 2, wseg = t & 3;
    unsigned hw[8];
    #pragma unroll
    for (int i = 0; i < 8; i++) {
        int j2 = wseg * 8 + i;
        hw[i] = packhf(sm[2*j2][row], sm[2*j2+1][row]);
    }
    size_t base = ((size_t)b * NTOKP + p0 + row) * 128 + k0/2 + wseg*8;
    *(uint4*)&g_xh[base]     = *(uint4*)&hw[0];
    *(uint4*)&g_xh[base + 4] = *(uint4*)&hw[4];
}

// ============================================================
// prep_vt: transpose+split V (bh,j,e) -> (bh,e,[j2]) fp16 h/l
// ============================================================
__global__ __launch_bounds__(256) void prep_vt() {
    __shared__ float sm[64][36];
    int jt = blockIdx.x, bh = blockIdx.y;
    int j0 = jt * 64, t = threadIdx.x;
    int j = t >> 2, e0 = (t & 3) * 8;
    const float* vb = g_v + (size_t)bh * NTOK * DH;
    if (j0 + j < NTOK) {
        *(float4*)&sm[j][e0]     = *(const float4*)&vb[(size_t)(j0+j) * DH + e0];
        *(float4*)&sm[j][e0 + 4] = *(const float4*)&vb[(size_t)(j0+j) * DH + e0 + 4];
    } else {
        #pragma unroll
        for (int i = 0; i < 8; i++) sm[j][e0 + i] = 0.f;
    }
    __syncthreads();
    int e = t >> 3, wseg = t & 7;
    unsigned hw[4], lw[4];
    #pragma unroll
    for (int i = 0; i < 4; i++) {
        int j2 = wseg * 4 + i;
        splith2(sm[2*j2][e], sm[2*j2+1][e], hw[i], lw[i]);
    }
    size_t base = ((size_t)bh * 32 + e) * 320 + jt*32 + wseg*4;
    *(uint4*)&g_vth[base] = *(uint4*)hw;
    *(uint4*)&g_vtl[base] = *(uint4*)lw;
}

// ============================================================
// Kernel 1: QKV projection. A=x single fp16, B=w split (2-term).
// Stage: Ah[128][20]=2560 | Bh[64][20]=1280 | Bl=1280 -> 5120 w.
// ============================================================
#define STG_Q 5120
#define QKV_SMEM (2*STG_Q*4)   // 40960 B

__global__ __launch_bounds__(256, 3) void qkv_mma() {
    extern __shared__ __align__(16) unsigned qsm[];
    int b  = blockIdx.z;
    int p0 = blockIdx.x * 128;
    int n0 = blockIdx.y * 64;
    int tid = threadIdx.x;
    int wid = tid >> 5, lane = tid & 31;
    int wm = wid & 3, wn = wid >> 2;
    int r = lane >> 2, c = lane & 3;
    unsigned smb = sptr(qsm);

    float4 acc[2][4];
    #pragma unroll
    for (int i = 0; i < 2; i++)
        #pragma unroll
        for (int j = 0; j < 4; j++) acc[i][j] = make_float4(0,0,0,0);

    int aRow = lane & 15;
    int aSel = (lane >> 4) * 4;
    int bRow = ((lane >> 4) << 3) | (lane & 7);
    int bSel = ((lane >> 3) & 1) * 4;

    int caRow = tid >> 1, caHalf = tid & 1;
    int cbRow = tid >> 2, cbSeg = tid & 3;
    size_t aSrc = ((size_t)b * NTOKP + p0 + caRow) * 128 + caHalf * 8;
    size_t bSrc = (size_t)(n0 + cbRow) * 128 + cbSeg * 4;

    auto copy_slab = [&](int slab, int buf) {
        unsigned sb = smb + buf * STG_Q * 4;
        unsigned dA = sb + (caRow*20 + caHalf*8) * 4;
        const unsigned* sh = g_xh + aSrc + slab*16;
        cpa16(dA,      sh);
        cpa16(dA + 16, sh + 4);
        unsigned dB = sb + (2560 + cbRow*20 + cbSeg*4) * 4;
        cpa16(dB,          g_wqh + bSrc + slab*16);
        cpa16(dB + 1280*4, g_wql + bSrc + slab*16);
    };

    copy_slab(0, 0);
    CP_COMMIT();
    int buf = 0;
    for (int s = 0; s < 8; s++) {
        CP_WAIT0();
        __syncthreads();
        if (s < 7) { copy_slab(s + 1, buf ^ 1); CP_COMMIT(); }

        unsigned AhB = smb + buf * STG_Q * 4;
        unsigned BhB = AhB + 2560 * 4;
        unsigned BlB = AhB + 3840 * 4;
        #pragma unroll
        for (int ktl = 0; ktl < 2; ktl++) {
            unsigned ah[2][4];
            #pragma unroll
            for (int mt = 0; mt < 2; mt++) {
                unsigned off = ((wm*32 + mt*16 + aRow) * 20 + ktl*8 + aSel) * 4u;
                ldsm4(ah[mt], AhB + off);
            }
            unsigned bhf[4][2], blf[4][2];
            #pragma unroll
            for (int ntp = 0; ntp < 2; ntp++) {
                unsigned off = ((wn*32 + ntp*16 + bRow) * 20 + ktl*8 + bSel) * 4u;
                unsigned t4[4];
                ldsm4(t4, BhB + off);
                bhf[2*ntp][0] = t4[0]; bhf[2*ntp][1] = t4[1];
                bhf[2*ntp+1][0] = t4[2]; bhf[2*ntp+1][1] = t4[3];
                ldsm4(t4, BlB + off);
                blf[2*ntp][0] = t4[0]; blf[2*ntp][1] = t4[1];
                blf[2*ntp+1][0] = t4[2]; blf[2*ntp+1][1] = t4[3];
            }
            #pragma unroll
            for (int nt = 0; nt < 4; nt++)
                #pragma unroll
                for (int mt = 0; mt < 2; mt++) {
                    mma16(acc[mt][nt], ah[mt], bhf[nt][0], bhf[nt][1]);
                    mma16(acc[mt][nt], ah[mt], blf[nt][0], blf[nt][1]);
                }
        }
        buf ^= 1;
    }

    // epilogue: Q split fp16, K single fp16, V fp32
    #pragma unroll
    for (int nt = 0; nt < 4; nt++) {
        int ng0 = n0 + wn * 32 + nt * 8 + 2 * c;
        int which = ng0 >> 8;
        int h = (ng0 >> 5) & 7;
        int e = ng0 & 31;
        int bhI = b * HEADS + h;
        #pragma unroll
        for (int mt = 0; mt < 2; mt++) {
            int p = p0 + wm * 32 + mt * 16 + r;
            float4 a = acc[mt][nt];
            if (which == 2) {
                if (p < NTOK)
                    *(float2*)&g_v[((size_t)bhI*NTOK + p)*DH + e] = make_float2(a.x, a.y);
                if (p + 8 < NTOK)
                    *(float2*)&g_v[((size_t)bhI*NTOK + p + 8)*DH + e] = make_float2(a.z, a.w);
            } else if (which == 0) {
                const float s = 0.17677669529663687f;
                size_t base = (size_t)bhI * NTOKP * 16 + (e >> 1);
                if (p < NTOK) {
                    unsigned hw, lw; splith2(a.x*s, a.y*s, hw, lw);
                    g_qh[base + (size_t)p*16] = hw; g_ql[base + (size_t)p*16] = lw;
                }
                if (p + 8 < NTOK) {
                    unsigned hw, lw; splith2(a.z*s, a.w*s, hw, lw);
                    g_qh[base + (size_t)(p+8)*16] = hw; g_ql[base + (size_t)(p+8)*16] = lw;
                }
            } else {
                size_t base = (size_t)bhI * NTOKP * 16 + (e >> 1);
                if (p < NTOK)
                    g_kh[base + (size_t)p*16] = packhf(a.x, a.y);
                if (p + 8 < NTOK)
                    g_kh[base + (size_t)(p+8)*16] = packhf(a.z, a.w);
            }
        }
    }
}

// ============================================================
// Kernel 2: flash attention. S: Q split x K single (2 mma);
// PV: P single x V split (2 mma). cp.async double-buffered.
// ============================================================
__global__ __launch_bounds__(256, 2) void attn_mma() {
    __shared__ __align__(16) unsigned Kh[2][64][20];
    __shared__ __align__(16) unsigned Vh[2][32][36], Vl[2][32][36];

    int tid = threadIdx.x;
    int wid = tid >> 5, lane = tid & 31;
    int r = lane >> 2, c = lane & 3;

    int q0 = blockIdx.x * 128;
    int bh = blockIdx.y;
    int h = bh & 7;

    int bRow = ((lane >> 4) << 3) | (lane & 7);
    int bSel = ((lane >> 3) & 1) * 4;

    int ckRow = tid >> 2, ckSeg = tid & 3;
    int cvRow = tid >> 3, cvSeg = tid & 7;
    size_t kSrc = ((size_t)bh * NTOKP + ckRow) * 16 + ckSeg * 4;
    size_t vSrc = ((size_t)bh * 32 + cvRow) * 320 + cvSeg * 4;

    auto copy_tile = [&](int jt, int buf) {
        cpa16(sptr(&Kh[buf][ckRow][ckSeg*4]), g_kh + kSrc + (size_t)jt*64*16);
        cpa16(sptr(&Vh[buf][cvRow][cvSeg*4]), g_vth + vSrc + jt*32);
        cpa16(sptr(&Vl[buf][cvRow][cvSeg*4]), g_vtl + vSrc + jt*32);
    };

    // Q fragments: pre-split fp16 words
    unsigned qh[2][4], ql[2][4];
    {
        const unsigned* qbh = g_qh + (size_t)bh * NTOKP * 16;
        const unsigned* qbl = g_ql + (size_t)bh * NTOKP * 16;
        int pr = q0 + wid * 16 + r;
        #pragma unroll
        for (int kt = 0; kt < 2; kt++) {
            qh[kt][0] = qbh[(size_t)pr*16     + kt*8 + c];
            qh[kt][1] = qbh[(size_t)(pr+8)*16 + kt*8 + c];
            qh[kt][2] = qbh[(size_t)pr*16     + kt*8 + c + 4];
            qh[kt][3] = qbh[(size_t)(pr+8)*16 + kt*8 + c + 4];
            ql[kt][0] = qbl[(size_t)pr*16     + kt*8 + c];
            ql[kt][1] = qbl[(size_t)(pr+8)*16 + kt*8 + c];
            ql[kt][2] = qbl[(size_t)pr*16     + kt*8 + c + 4];
            ql[kt][3] = qbl[(size_t)(pr+8)*16 + kt*8 + c + 4];
        }
    }

    float4 O[4];
    #pragma unroll
    for (int i = 0; i < 4; i++) O[i] = make_float4(0,0,0,0);
    float m0 = -INFINITY, m1 = -INFINITY, l0 = 0.f, l1 = 0.f;

    copy_tile(0, 0);
    CP_COMMIT();
    int buf = 0;
    for (int jt = 0; jt < 10; jt++) {
        int j0 = jt * 64;
        CP_WAIT0();
        __syncthreads();
        if (jt < 9) { copy_tile(jt + 1, buf ^ 1); CP_COMMIT(); }

        unsigned KhB = sptr(Kh) + buf * 64*20*4;
        unsigned VhB = sptr(Vh) + buf * 32*36*4;
        unsigned VlB = sptr(Vl) + buf * 32*36*4;

        // ---- S = Q K^T (K single: 4 mma per ntp) ----
        float4 acc[8];
        #pragma unroll
        for (int i = 0; i < 8; i++) acc[i] = make_float4(0,0,0,0);
        #pragma unroll
        for (int kt = 0; kt < 2; kt++) {
            #pragma unroll
            for (int ntp = 0; ntp < 4; ntp++) {
                unsigned off = ((ntp*16 + bRow) * 20 + kt*8 + bSel) * 4u;
                unsigned th[4];
                ldsm4(th, KhB + off);
                mma16(acc[2*ntp  ], qh[kt], th[0], th[1]);
                mma16(acc[2*ntp  ], ql[kt], th[0], th[1]);
                mma16(acc[2*ntp+1], qh[kt], th[2], th[3]);
                mma16(acc[2*ntp+1], ql[kt], th[2], th[3]);
            }
        }

        // ---- bias + tail mask ----
        {
            const float* bp = g_bias + ((size_t)(h * NPAD + q0 + wid*16 + r)) * NPAD + j0;
            #pragma unroll
            for (int nt = 0; nt < 8; nt++) {
                float2 b0v = *(const float2*)&bp[nt*8 + 2*c];
                float2 b1v = *(const float2*)&bp[8*NPAD + nt*8 + 2*c];
                acc[nt].x += b0v.x; acc[nt].y += b0v.y;
                acc[nt].z += b1v.x; acc[nt].w += b1v.y;
            }
            if (j0 + 64 > NTOK) {
                #pragma unroll
                for (int nt = 0; nt < 8; nt++) {
                    int jc = j0 + nt*8 + 2*c;
                    if (jc     >= NTOK) { acc[nt].x = -1e30f; acc[nt].z = -1e30f; }
                    if (jc + 1 >= NTOK) { acc[nt].y = -1e30f; acc[nt].w = -1e30f; }
                }
            }
        }

        // ---- online softmax (quad reduce) ----
        float t0 = -INFINITY, t1 = -INFINITY;
        #pragma unroll
        for (int nt = 0; nt < 8; nt++) {
            t0 = fmaxf(t0, fmaxf(acc[nt].x, acc[nt].y));
            t1 = fmaxf(t1, fmaxf(acc[nt].z, acc[nt].w));
        }
        #pragma unroll
        for (int off = 1; off <= 2; off <<= 1) {
            t0 = fmaxf(t0, __shfl_xor_sync(0xffffffffu, t0, off));
            t1 = fmaxf(t1, __shfl_xor_sync(0xffffffffu, t1, off));
        }
        float mn0 = fmaxf(m0, t0), mn1 = fmaxf(m1, t1);
        float cor0 = __expf(m0 - mn0), cor1 = __expf(m1 - mn1);
        float s0 = 0.f, s1 = 0.f;
        #pragma unroll
        for (int nt = 0; nt < 8; nt++) {
            acc[nt].x = __expf(acc[nt].x - mn0);
            acc[nt].y = __expf(acc[nt].y - mn0);
            acc[nt].z = __expf(acc[nt].z - mn1);
            acc[nt].w = __expf(acc[nt].w - mn1);
            s0 += acc[nt].x + acc[nt].y;
            s1 += acc[nt].z + acc[nt].w;
        }
        #pragma unroll
        for (int off = 1; off <= 2; off <<= 1) {
            s0 += __shfl_xor_sync(0xffffffffu, s0, off);
            s1 += __shfl_xor_sync(0xffffffffu, s1, off);
        }
        l0 = l0 * cor0 + s0;  m0 = mn0;
        l1 = l1 * cor1 + s1;  m1 = mn1;
        #pragma unroll
        for (int i = 0; i < 4; i++) {
            O[i].x *= cor0; O[i].y *= cor0;
            O[i].z *= cor1; O[i].w *= cor1;
        }

        // ---- O += P V (P single pack; V split) ----
        #pragma unroll
        for (int kt = 0; kt < 4; kt++) {
            unsigned ph[4];
            ph[0] = packhf(acc[2*kt  ].x, acc[2*kt  ].y);
            ph[1] = packhf(acc[2*kt  ].z, acc[2*kt  ].w);
            ph[2] = packhf(acc[2*kt+1].x, acc[2*kt+1].y);
            ph[3] = packhf(acc[2*kt+1].z, acc[2*kt+1].w);
            #pragma unroll
            for (int ntp = 0; ntp < 2; ntp++) {
                unsigned off = ((ntp*16 + bRow) * 36 + kt*8 + bSel) * 4u;
                unsigned th[4], tl[4];
                ldsm4(th, VhB + off);
                ldsm4(tl, VlB + off);
                mma16(O[2*ntp  ], ph, th[0], th[1]);
                mma16(O[2*ntp  ], ph, tl[0], tl[1]);
                mma16(O[2*ntp+1], ph, th[2], th[3]);
                mma16(O[2*ntp+1], ph, tl[2], tl[3]);
            }
        }
        buf ^= 1;
    }

    // epilogue: O split fp16 -> g_oh/g_ol (b, p, [word])
    float inv0 = 1.f / l0, inv1 = 1.f / l1;
    size_t ob = (size_t)(bh >> 3) * NTOKP * 128 + h * 16;
    #pragma unroll
    for (int nt = 0; nt < 4; nt++) {
        int w2 = nt * 4 + c;
        int p = q0 + wid * 16 + r;
        if (p < NTOK) {
            unsigned hw, lw; splith2(O[nt].x * inv0, O[nt].y * inv0, hw, lw);
            g_oh[ob + (size_t)p*128 + w2] = hw;
            g_ol[ob + (size_t)p*128 + w2] = lw;
        }
        if (p + 8 < NTOK) {
            unsigned hw, lw; splith2(O[nt].z * inv1, O[nt].w * inv1, hw, lw);
            g_oh[ob + (size_t)(p+8)*128 + w2] = hw;
            g_ol[ob + (size_t)(p+8)*128 + w2] = lw;
        }
    }
}

// ============================================================
// Kernel 3: output projection. A=O split, B=w_out single (2-term).
// Stage: Ah 2560 | Al 2560 | Bh 1280 -> 6400 words.
// ============================================================
#define STG_O 6400
#define OUT_SMEM (2*STG_O*4)   // 51200 B

__global__ __launch_bounds__(256, 3) void out_mma(float* __restrict__ out) {
    extern __shared__ __align__(16) unsigned osm[];
    float (*Cs)[69] = (float(*)[69])osm;

    int b  = blockIdx.z;
    int p0 = blockIdx.x * 128;
    int n0 = blockIdx.y * 64;
    int tid = threadIdx.x;
    int wid = tid >> 5, lane = tid & 31;
    int wm = wid & 3, wn = wid >> 2;
    int r = lane >> 2, c = lane & 3;
    unsigned smb = sptr(osm);

    float4 acc[2][4];
    #pragma unroll
    for (int i = 0; i < 2; i++)
        #pragma unroll
        for (int j = 0; j < 4; j++) acc[i][j] = make_float4(0,0,0,0);

    int aRow = lane & 15;
    int aSel = (lane >> 4) * 4;
    int bRow = ((lane >> 4) << 3) | (lane & 7);
    int bSel = ((lane >> 3) & 1) * 4;

    int caRow = tid >> 1, caHalf = tid & 1;
    int cbRow = tid >> 2, cbSeg = tid & 3;
    size_t aSrc = ((size_t)b * NTOKP + p0 + caRow) * 128 + caHalf * 8;
    size_t bSrc = (size_t)(n0 + cbRow) * 128 + cbSeg * 4;

    auto copy_slab = [&](int slab, int buf) {
        unsigned sb = smb + buf * STG_O * 4;
        unsigned dA  = sb + (caRow*20 + caHalf*8) * 4;
        unsigned dAl = dA + 2560 * 4;
        const unsigned* sh = g_oh + aSrc + slab*16;
        const unsigned* sl = g_ol + aSrc + slab*16;
        cpa16(dA,       sh);  cpa16(dA  + 16, sh + 4);
        cpa16(dAl,      sl);  cpa16(dAl + 16, sl + 4);
        unsigned dB = sb + (5120 + cbRow*20 + cbSeg*4) * 4;
        cpa16(dB, g_woh + bSrc + slab*16);
    };

    copy_slab(0, 0);
    CP_COMMIT();
    int buf = 0;
    for (int s = 0; s < 8; s++) {
        CP_WAIT0();
        __syncthreads();
        if (s < 7) { copy_slab(s + 1, buf ^ 1); CP_COMMIT(); }

        unsigned AhB = smb + buf * STG_O * 4;
        unsigned AlB = AhB + 2560 * 4;
        unsigned BhB = AhB + 5120 * 4;
        #pragma unroll
        for (int ktl = 0; ktl < 2; ktl++) {
            unsigned ah[2][4], al[2][4];
            #pragma unroll
            for (int mt = 0; mt < 2; mt++) {
                unsigned off = ((wm*32 + mt*16 + aRow) * 20 + ktl*8 + aSel) * 4u;
                ldsm4(ah[mt], AhB + off);
                ldsm4(al[mt], AlB + off);
            }
            unsigned bhf[4][2];
            #pragma unroll
            for (int ntp = 0; ntp < 2; ntp++) {
                unsigned off = ((wn*32 + ntp*16 + bRow) * 20 + ktl*8 + bSel) * 4u;
                unsigned t4[4];
                ldsm4(t4, BhB + off);
                bhf[2*ntp][0] = t4[0]; bhf[2*ntp][1] = t4[1];
                bhf[2*ntp+1][0] = t4[2]; bhf[2*ntp+1][1] = t4[3];
            }
            #pragma unroll
            for (int nt = 0; nt < 4; nt++)
                #pragma unroll
                for (int mt = 0; mt < 2; mt++) {
                    mma16(acc[mt][nt], ah[mt], bhf[nt][0], bhf[nt][1]);
                    mma16(acc[mt][nt], al[mt], bhf[nt][0], bhf[nt][1]);
                }
        }
        buf ^= 1;
    }

    __syncthreads();   // staging done before Cs reuse

    #pragma unroll
    for (int mt = 0; mt < 2; mt++) {
        int m = wm * 32 + mt * 16 + r;
        #pragma unroll
        for (int nt = 0; nt < 4; nt++) {
            int n = wn * 32 + nt * 8 + 2 * c;
            Cs[m    ][n    ] = acc[mt][nt].x;
            Cs[m    ][n + 1] = acc[mt][nt].y;
            Cs[m + 8][n    ] = acc[mt][nt].z;
            Cs[m + 8][n + 1] = acc[mt][nt].w;
        }
    }
    __syncthreads();

    #pragma unroll
    for (int it = 0; it < 32; it++) {
        int idx = it * 256 + tid;
        int n = idx >> 7;
        int m = idx & 127;
        int p = p0 + m;
        if (p < NTOK)
            out[((size_t)b * DD + n0 + n) * NTOK + p] = Cs[m][n];
    }
}

// ============================================================
extern "C" void kernel_launch(void* const* d_in, const int* in_sizes, int n_in,
                              void* d_out, int out_size) {
    const float* x          = (const float*)d_in[0];
    const float* w_qkv      = (const float*)d_in[1];
    const float* w_out      = (const float*)d_in[2];
    const float* bias_table = (const float*)d_in[3];
    const int*   rel        = (const int*)d_in[4];
    float* out = (float*)d_out;

    cudaFuncSetAttribute(qkv_mma, cudaFuncAttributeMaxDynamicSharedMemorySize,
                         QKV_SMEM);
    cudaFuncSetAttribute(out_mma, cudaFuncAttributeMaxDynamicSharedMemorySize,
                         OUT_SMEM);

    bias_fill<<<(HEADS * NTOK * NTOK + 255) / 256, 256>>>(bias_table, rel);
    prep_w<<<512, 256>>>(w_qkv, w_out);
    prep_x<<<dim3(10, 4, BB), 256>>>(x);
    qkv_mma<<<dim3(5, 12, BB), 256, QKV_SMEM>>>();
    prep_vt<<<dim3(10, NBH), 256>>>();
    attn_mma<<<dim3(5, NBH), 256>>>();
    out_mma<<<dim3(5, 4, BB), 256, OUT_SMEM>>>(out);
}